// round 8
// baseline (speedup 1.0000x reference)
#include <cuda_runtime.h>
#include <cuda_bf16.h>
#include <math.h>
#include <stdint.h>

#define D_MODEL 2048
#define N_HEADS 16
#define D_CQ    1536
#define D_C     512
#define D_H     128
#define D_R     64
#define BSZ     4
#define SEQ     2048
#define NTOK    (BSZ*SEQ)
#define D_QK    (D_H + D_R)
#define LL long long

#define SW64(o)  ((o) ^ (((o) >> 2) & 0x30))

typedef __nv_bfloat16 bf16;

// ---------------- scratch ----------------
__device__ float g_tmp1[(LL)NTOK * D_CQ];
__device__ float g_tmp2[(LL)NTOK * D_C];
__device__ float g_qC  [(LL)NTOK * 2048];
__device__ float g_qR  [(LL)NTOK * 1024];
__device__ float g_kr  [(LL)NTOK * D_R];
__device__ float g_krn [(LL)NTOK * D_R];
__device__ float g_kC  [(LL)NTOK * 2048];
__device__ float g_vC  [(LL)NTOK * 2048];
__device__ float g_attnf[(LL)NTOK * 2048];
// int8 slices + scales
__device__ int8_t g_h1[(LL)NTOK*D_MODEL],   g_h2[(LL)NTOK*D_MODEL];
__device__ float  g_sh[NTOK];
__device__ int8_t g_Wqd1[(LL)D_CQ*D_MODEL], g_Wqd2[(LL)D_CQ*D_MODEL];
__device__ float  g_sWqd[D_CQ];
__device__ int8_t g_Wqc1[(LL)2048*D_CQ],    g_Wqc2[(LL)2048*D_CQ];
__device__ float  g_sWqc[2048];
__device__ int8_t g_Wqr1[(LL)1024*D_CQ],    g_Wqr2[(LL)1024*D_CQ];
__device__ float  g_sWqr[1024];
__device__ int8_t g_Wkv1[(LL)D_C*D_MODEL],  g_Wkv2[(LL)D_C*D_MODEL];
__device__ float  g_sWkv[D_C];
__device__ int8_t g_Wkc1[(LL)2048*D_C],     g_Wkc2[(LL)2048*D_C];
__device__ float  g_sWkc[2048];
__device__ int8_t g_Wvc1[(LL)2048*D_C],     g_Wvc2[(LL)2048*D_C];
__device__ float  g_sWvc[2048];
__device__ int8_t g_Wo1[(LL)2048*2048],     g_Wo2[(LL)2048*2048];
__device__ float  g_sWo[2048];
__device__ int8_t g_cQ1[(LL)NTOK*D_CQ],     g_cQ2[(LL)NTOK*D_CQ];
__device__ float  g_scQ[NTOK];
__device__ int8_t g_cKV1[(LL)NTOK*D_C],     g_cKV2[(LL)NTOK*D_C];
__device__ float  g_scKV[NTOK];
__device__ int8_t g_at1[(LL)NTOK*2048],     g_at2[(LL)NTOK*2048];
__device__ float  g_sat[NTOK];
// bf16 splits (attention path)
__device__ bf16 g_qf_hi[(LL)NTOK*N_HEADS*D_QK], g_qf_lo[(LL)NTOK*N_HEADS*D_QK];
__device__ bf16 g_kf_hi[(LL)NTOK*N_HEADS*D_QK], g_kf_lo[(LL)NTOK*N_HEADS*D_QK];
__device__ bf16 g_vCT_hi[(LL)2048*NTOK],        g_vCT_lo[(LL)2048*NTOK];
__device__ bf16 g_w_hi[(LL)BSZ*N_HEADS*SEQ*SEQ], g_w_lo[(LL)BSZ*N_HEADS*SEQ*SEQ];

// ---------------- helpers ----------------
__device__ __forceinline__ uint32_t smem_u32(const void* p) {
    uint32_t a;
    asm("{ .reg .u64 t; cvta.to.shared.u64 t, %1; cvt.u32.u64 %0, t; }" : "=r"(a) : "l"(p));
    return a;
}
#define CP16(d, s) asm volatile("cp.async.cg.shared.global [%0], [%1], 16;" :: "r"(d), "l"(s))
#define CP_COMMIT() asm volatile("cp.async.commit_group;" ::: "memory")
#define CP_WAIT1() asm volatile("cp.async.wait_group 1;" ::: "memory")

__device__ __forceinline__ void ldsm_x4(uint32_t addr, uint32_t& r0, uint32_t& r1,
                                        uint32_t& r2, uint32_t& r3) {
    asm volatile("ldmatrix.sync.aligned.m8n8.x4.shared.b16 {%0,%1,%2,%3}, [%4];"
                 : "=r"(r0), "=r"(r1), "=r"(r2), "=r"(r3) : "r"(addr));
}
__device__ __forceinline__ void mma_bf16(float* c, const uint32_t* a,
                                         uint32_t b0, uint32_t b1) {
    asm volatile(
        "mma.sync.aligned.m16n8k16.row.col.f32.bf16.bf16.f32 "
        "{%0,%1,%2,%3}, {%4,%5,%6,%7}, {%8,%9}, {%0,%1,%2,%3};"
        : "+f"(c[0]), "+f"(c[1]), "+f"(c[2]), "+f"(c[3])
        : "r"(a[0]), "r"(a[1]), "r"(a[2]), "r"(a[3]), "r"(b0), "r"(b1));
}
__device__ __forceinline__ void mma_s8(int* c, const uint32_t* a,
                                       uint32_t b0, uint32_t b1) {
    asm volatile(
        "mma.sync.aligned.m16n8k32.row.col.s32.s8.s8.s32 "
        "{%0,%1,%2,%3}, {%4,%5,%6,%7}, {%8,%9}, {%0,%1,%2,%3};"
        : "+r"(c[0]), "+r"(c[1]), "+r"(c[2]), "+r"(c[3])
        : "r"(a[0]), "r"(a[1]), "r"(a[2]), "r"(a[3]), "r"(b0), "r"(b1));
}
__device__ __forceinline__ void splitw(float v, bf16& hi, bf16& lo) {
    hi = __float2bfloat16(v);
    lo = __float2bfloat16(v - __bfloat162float(hi));
}

// ============ int8 2-slice GEMM: 128x128 tile, 512 thr (16 warps), BK=64, 3-stage ============
// A slices [M][K], B slices [N][K], scales sA[M], sB[N].  K % 64 == 0.
__global__ __launch_bounds__(512, 1)
void gemm_i8(const int8_t* __restrict__ A1, const int8_t* __restrict__ A2,
             const int8_t* __restrict__ B1, const int8_t* __restrict__ B2,
             const float* __restrict__ sA, const float* __restrict__ sB,
             const float* __restrict__ bias, float* __restrict__ C,
             int K, int N)
{
    int m0 = blockIdx.y * 128;
    int n0 = blockIdx.x * 128;

    extern __shared__ char sm[];
    uint32_t sb = smem_u32(sm);

    int tid = threadIdx.x;
    int wid = tid >> 5, lane = tid & 31;
    int wm = (wid & 7) << 4;      // 8 warps along m: 16 rows each
    int wn = (wid >> 3) << 6;     // 2 warps along n: 64 cols each
    int g = lane >> 3, r = lane & 7;
    int aro = ((g & 1) << 3) + r, aco = (g >> 1) << 4;
    int bro = ((g >> 1) << 3) + r, bco = (g & 1) << 4;

    int acc1[8][4], acc2[8][4];
    #pragma unroll
    for (int j = 0; j < 8; j++)
        #pragma unroll
        for (int t = 0; t < 4; t++) { acc1[j][t] = 0; acc2[j][t] = 0; }

    // stage: A1 8K | A2 8K | B1 8K | B2 8K = 32KB; 3 stages = 96KB
    #define ILOAD(s, k0) do {                                                  \
        uint32_t st = sb + (uint32_t)(s) * 32768u;                             \
        int row = tid >> 2, c = (tid & 3) << 4;                                \
        uint32_t sw = SW64((uint32_t)((row << 6) + c));                        \
        LL goA = (LL)(m0 + row) * K + (k0) + c;                                \
        LL goB = (LL)(n0 + row) * K + (k0) + c;                                \
        CP16(st + sw,           A1 + goA);                                     \
        CP16(st + 8192u  + sw,  A2 + goA);                                     \
        CP16(st + 16384u + sw,  B1 + goB);                                     \
        CP16(st + 24576u + sw,  B2 + goB);                                     \
    } while (0)

    const int KT = K >> 6;
    ILOAD(0, 0);  CP_COMMIT();
    ILOAD(1, 64); CP_COMMIT();

    int cs = 0, ls = 2;
    for (int kt = 0; kt < KT; kt++) {
        CP_WAIT1();
        __syncthreads();
        if (kt + 2 < KT) {
            ILOAD(ls, (kt + 2) << 6);
        }
        CP_COMMIT();
        ls++; if (ls == 3) ls = 0;

        uint32_t aB = sb + (uint32_t)cs * 32768u;
        uint32_t bB = aB + 16384u;

        #pragma unroll
        for (int ks = 0; ks < 2; ks++) {
            int kb = ks << 5;   // 32 int8 = 32 bytes
            uint32_t a1f[4], a2f[4];
            {
                uint32_t off = SW64((uint32_t)((wm + aro) * 64 + kb + aco));
                ldsm_x4(aB + off,         a1f[0], a1f[1], a1f[2], a1f[3]);
                ldsm_x4(aB + 8192u + off, a2f[0], a2f[1], a2f[2], a2f[3]);
            }
            #pragma unroll
            for (int ng = 0; ng < 4; ng++) {
                uint32_t off = SW64((uint32_t)((wn + (ng << 4) + bro) * 64 + kb + bco));
                uint32_t p0, p1, p2, p3, q0, q1, q2, q3;
                ldsm_x4(bB + off,         p0, p1, p2, p3);
                ldsm_x4(bB + 8192u + off, q0, q1, q2, q3);
                int* c1a = acc1[(ng << 1)];
                int* c1b = acc1[(ng << 1) + 1];
                int* c2a = acc2[(ng << 1)];
                int* c2b = acc2[(ng << 1) + 1];
                mma_s8(c1a, a1f, p0, p1);
                mma_s8(c1b, a1f, p2, p3);
                mma_s8(c2a, a1f, q0, q1);
                mma_s8(c2b, a1f, q2, q3);
                mma_s8(c2a, a2f, p0, p1);
                mma_s8(c2b, a2f, p2, p3);
            }
        }
        cs++; if (cs == 3) cs = 0;
    }

    const float inv254 = 1.0f / 254.0f;
    int row = m0 + wm + (lane >> 2);
    float sa0 = sA[row], sa1 = sA[row + 8];
    #pragma unroll
    for (int nf = 0; nf < 8; nf++) {
        int col = n0 + wn + (nf << 3) + ((lane & 3) << 1);
        float sb0 = sB[col], sb1 = sB[col + 1];
        float bx = bias[col], by = bias[col + 1];
        int* c1 = acc1[nf];
        int* c2 = acc2[nf];
        float v00 = sa0 * sb0 * ((float)c1[0] + (float)c2[0] * inv254) + bx;
        float v01 = sa0 * sb1 * ((float)c1[1] + (float)c2[1] * inv254) + by;
        float v10 = sa1 * sb0 * ((float)c1[2] + (float)c2[2] * inv254) + bx;
        float v11 = sa1 * sb1 * ((float)c1[3] + (float)c2[3] * inv254) + by;
        *(float2*)(C + (LL)row * N + col)       = make_float2(v00, v01);
        *(float2*)(C + (LL)(row + 8) * N + col) = make_float2(v10, v11);
    }
}

// ============ bf16x3 GEMM: 128x128 tile, BK=32, 3-stage, 2 CTAs/SM (attention path) ============
// EPI: 1 = fp32, 2 = bf16 hi/lo splits.
template<int EPI, bool CAUSAL, bool KCLIP>
__global__ __launch_bounds__(256, 2)
void gemm128(const bf16* __restrict__ Ahi, const bf16* __restrict__ Alo,
             const bf16* __restrict__ Bhi, const bf16* __restrict__ Blo,
             float* __restrict__ C, bf16* __restrict__ Chi, bf16* __restrict__ Clo,
             int K, int lda, int ldb, int ldc,
             LL soA, LL siA, LL soB, LL siB, LL soC, LL siC, int IC)
{
    int m0 = blockIdx.y * 128;
    int n0 = blockIdx.x * 128;
    if (CAUSAL && n0 > m0) return;

    int z = blockIdx.z;
    LL zo = z / IC, zi = z % IC;
    const bf16* Ah_b = Ahi + zo*soA + zi*siA;
    const bf16* Al_b = Alo + zo*soA + zi*siA;
    const bf16* Bh_b = Bhi + zo*soB + zi*siB;
    const bf16* Bl_b = Blo + zo*soB + zi*siB;

    int Keff = KCLIP ? (m0 + 128 < K ? m0 + 128 : K) : K;
    int KT = Keff >> 5;

    extern __shared__ char sm[];
    uint32_t sb = smem_u32(sm);

    int tid = threadIdx.x;
    int wid = tid >> 5, lane = tid & 31;
    int wm = (wid & 3) << 5;
    int wn = (wid >> 2) << 6;
    int g = lane >> 3, r = lane & 7;
    int aro = ((g & 1) << 3) + r, aco = (g >> 1) << 4;
    int bro = ((g >> 1) << 3) + r, bco = (g & 1) << 4;

    float acc[2][8][4];
    #pragma unroll
    for (int i = 0; i < 2; i++)
        #pragma unroll
        for (int j = 0; j < 8; j++)
            #pragma unroll
            for (int t = 0; t < 4; t++) acc[i][j][t] = 0.0f;

    #define GLOAD(s, k0) do {                                                  \
        uint32_t st = sb + (uint32_t)(s) * 32768u;                             \
        _Pragma("unroll")                                                      \
        for (int i = 0; i < 2; i++) {                                          \
            int idx = tid + (i << 8);                                          \
            int row = idx >> 2, c = (idx & 3) << 4;                            \
            uint32_t sw = SW64((uint32_t)((row << 6) + c));                    \
            LL goA = (LL)(m0 + row) * lda + (k0) + ((idx & 3) << 3);           \
            LL goB = (LL)(n0 + row) * ldb + (k0) + ((idx & 3) << 3);           \
            CP16(st + sw,           Ah_b + goA);                               \
            CP16(st + 8192u  + sw,  Al_b + goA);                               \
            CP16(st + 16384u + sw,  Bh_b + goB);                               \
            CP16(st + 24576u + sw,  Bl_b + goB);                               \
        }                                                                      \
    } while (0)

    GLOAD(0, 0);  CP_COMMIT();
    GLOAD(1, 32); CP_COMMIT();

    int cs = 0, ls = 2;
    for (int kt = 0; kt < KT; kt++) {
        CP_WAIT1();
        __syncthreads();
        if (kt + 2 < KT) {
            GLOAD(ls, (kt + 2) << 5);
        }
        CP_COMMIT();
        ls++; if (ls == 3) ls = 0;

        uint32_t aB = sb + (uint32_t)cs * 32768u;
        uint32_t bB = aB + 16384u;

        #pragma unroll
        for (int ks = 0; ks < 2; ks++) {
            int kb = ks << 5;
            uint32_t ah[2][4], al[2][4];
            #pragma unroll
            for (int mf = 0; mf < 2; mf++) {
                uint32_t off = SW64((uint32_t)((wm + (mf << 4) + aro) * 64 + kb + aco));
                ldsm_x4(aB + off,         ah[mf][0], ah[mf][1], ah[mf][2], ah[mf][3]);
                ldsm_x4(aB + 8192u + off, al[mf][0], al[mf][1], al[mf][2], al[mf][3]);
            }
            #pragma unroll
            for (int ng = 0; ng < 4; ng++) {
                uint32_t off = SW64((uint32_t)((wn + (ng << 4) + bro) * 64 + kb + bco));
                uint32_t bh0, bh1, bh2, bh3, bl0, bl1, bl2, bl3;
                ldsm_x4(bB + off,         bh0, bh1, bh2, bh3);
                ldsm_x4(bB + 8192u + off, bl0, bl1, bl2, bl3);
                #pragma unroll
                for (int mf = 0; mf < 2; mf++) {
                    float* c0 = acc[mf][(ng << 1)];
                    float* c1 = acc[mf][(ng << 1) + 1];
                    mma_bf16(c0, ah[mf], bh0, bh1);
                    mma_bf16(c1, ah[mf], bh2, bh3);
                    mma_bf16(c0, ah[mf], bl0, bl1);
                    mma_bf16(c1, ah[mf], bl2, bl3);
                    mma_bf16(c0, al[mf], bh0, bh1);
                    mma_bf16(c1, al[mf], bh2, bh3);
                }
            }
        }
        cs++; if (cs == 3) cs = 0;
    }

    #pragma unroll
    for (int mf = 0; mf < 2; mf++) {
        int row = m0 + wm + (mf << 4) + (lane >> 2);
        #pragma unroll
        for (int nf = 0; nf < 8; nf++) {
            int col = n0 + wn + (nf << 3) + ((lane & 3) << 1);
            float* a = acc[mf][nf];
            if (EPI == 1) {
                float* Cb = C + zo*soC + zi*siC;
                *(float2*)(Cb + (LL)row * ldc + col)       = make_float2(a[0], a[1]);
                *(float2*)(Cb + (LL)(row + 8) * ldc + col) = make_float2(a[2], a[3]);
            } else {
                bf16* Hb = Chi + zo*soC + zi*siC;
                bf16* Lb = Clo + zo*soC + zi*siC;
                bf16 h0, l0, h1, l1;
                splitw(a[0], h0, l0); splitw(a[1], h1, l1);
                uint32_t hp = ((uint32_t)__bfloat16_as_ushort(h1) << 16) | __bfloat16_as_ushort(h0);
                uint32_t lp = ((uint32_t)__bfloat16_as_ushort(l1) << 16) | __bfloat16_as_ushort(l0);
                *(uint32_t*)(Hb + (LL)row * ldc + col) = hp;
                *(uint32_t*)(Lb + (LL)row * ldc + col) = lp;
                splitw(a[2], h0, l0); splitw(a[3], h1, l1);
                hp = ((uint32_t)__bfloat16_as_ushort(h1) << 16) | __bfloat16_as_ushort(h0);
                lp = ((uint32_t)__bfloat16_as_ushort(l1) << 16) | __bfloat16_as_ushort(l0);
                *(uint32_t*)(Hb + (LL)(row + 8) * ldc + col) = hp;
                *(uint32_t*)(Lb + (LL)(row + 8) * ldc + col) = lp;
            }
        }
    }
}

// ---------------- quant kernels ----------------
__global__ __launch_bounds__(256)
void quant_rows(const float* __restrict__ x, int8_t* __restrict__ q1,
                int8_t* __restrict__ q2, float* __restrict__ s, int dim)
{
    LL base = (LL)blockIdx.x * dim;
    int tid = threadIdx.x;
    int cnt = dim >> 8;
    float v[8];
    float mx = 0.0f;
    #pragma unroll 8
    for (int i = 0; i < cnt; i++) {
        v[i] = x[base + tid + (i << 8)];
        mx = fmaxf(mx, fabsf(v[i]));
    }
    __shared__ float red[256];
    red[tid] = mx; __syncthreads();
    for (int st = 128; st > 0; st >>= 1) {
        if (tid < st) red[tid] = fmaxf(red[tid], red[tid + st]);
        __syncthreads();
    }
    float sc = fmaxf(red[0], 1e-20f) * (1.0f / 127.0f);
    if (tid == 0) s[blockIdx.x] = sc;
    float isc = 1.0f / sc;
    #pragma unroll 8
    for (int i = 0; i < cnt; i++) {
        float q = v[i] * isc;
        float i1 = rintf(q);
        float i2 = rintf((q - i1) * 254.0f);
        q1[base + tid + (i << 8)] = (int8_t)(int)i1;
        q2[base + tid + (i << 8)] = (int8_t)(int)i2;
    }
}

__global__ __launch_bounds__(256)
void rmsnorm_quant(const float* __restrict__ x, const float* __restrict__ g,
                   int8_t* __restrict__ q1, int8_t* __restrict__ q2,
                   float* __restrict__ s, int dim)
{
    LL base = (LL)blockIdx.x * dim;
    int tid = threadIdx.x;
    int cnt = dim >> 8;
    float v[8];
    float ss = 0.0f;
    #pragma unroll 8
    for (int i = 0; i < cnt; i++) {
        v[i] = x[base + tid + (i << 8)];
        ss += v[i] * v[i];
    }
    __shared__ float red[256];
    red[tid] = ss; __syncthreads();
    for (int st = 128; st > 0; st >>= 1) {
        if (tid < st) red[tid] += red[tid + st];
        __syncthreads();
    }
    float rs = rsqrtf(red[0] / (float)dim + 1e-6f);
    __syncthreads();
    float mx = 0.0f;
    #pragma unroll 8
    for (int i = 0; i < cnt; i++) {
        v[i] = v[i] * rs * g[tid + (i << 8)];
        mx = fmaxf(mx, fabsf(v[i]));
    }
    red[tid] = mx; __syncthreads();
    for (int st = 128; st > 0; st >>= 1) {
        if (tid < st) red[tid] = fmaxf(red[tid], red[tid + st]);
        __syncthreads();
    }
    float sc = fmaxf(red[0], 1e-20f) * (1.0f / 127.0f);
    if (tid == 0) s[blockIdx.x] = sc;
    float isc = 1.0f / sc;
    #pragma unroll 8
    for (int i = 0; i < cnt; i++) {
        float q = v[i] * isc;
        float i1 = rintf(q);
        float i2 = rintf((q - i1) * 254.0f);
        q1[base + tid + (i << 8)] = (int8_t)(int)i1;
        q2[base + tid + (i << 8)] = (int8_t)(int)i2;
    }
}

// column max of W[K][N] -> s[N]; 32 cols per block, 8 row-groups of 32 threads
__global__ __launch_bounds__(256)
void colmax2(const float* __restrict__ W, float* __restrict__ s, int K, int N)
{
    __shared__ float red[8][32];
    int tid = threadIdx.x;
    int cl = tid & 31, grp = tid >> 5;
    int n = blockIdx.x * 32 + cl;
    float m = 0.0f;
    for (int k = grp; k < K; k += 8)
        m = fmaxf(m, fabsf(W[(LL)k * N + n]));
    red[grp][cl] = m;
    __syncthreads();
    if (grp == 0) {
        #pragma unroll
        for (int j = 1; j < 8; j++) m = fmaxf(m, red[j][cl]);
        s[n] = fmaxf(m, 1e-20f) * (1.0f / 127.0f);
    }
}

// W[R][C] fp32 -> T[C][R] int8 slices with per-output-row scale s[C]
__global__ __launch_bounds__(256)
void quant_tr(const float* __restrict__ x, const float* __restrict__ s,
              int8_t* __restrict__ t1, int8_t* __restrict__ t2, int R, int C)
{
    __shared__ float smt[32][33];
    int tx = threadIdx.x & 31, ty = threadIdx.x >> 5;
    int r0 = blockIdx.y * 32, c0 = blockIdx.x * 32;
    #pragma unroll
    for (int j = 0; j < 4; j++)
        smt[ty + 8*j][tx] = x[(LL)(r0 + ty + 8*j) * C + c0 + tx];
    __syncthreads();
    #pragma unroll
    for (int j = 0; j < 4; j++) {
        int n = c0 + ty + 8*j;
        float isc = 1.0f / s[n];
        float q = smt[tx][ty + 8*j] * isc;
        float i1 = rintf(q);
        float i2 = rintf((q - i1) * 254.0f);
        LL o = (LL)n * R + r0 + tx;
        t1[o] = (int8_t)(int)i1;
        t2[o] = (int8_t)(int)i2;
    }
}

// fp32 [R][C] -> [C][R] bf16 hi/lo
__global__ __launch_bounds__(256)
void split_tr(const float* __restrict__ x, bf16* __restrict__ hi, bf16* __restrict__ lo,
              int R, int C)
{
    __shared__ float smt[32][33];
    int tx = threadIdx.x & 31, ty = threadIdx.x >> 5;
    int r0 = blockIdx.y * 32, c0 = blockIdx.x * 32;
    #pragma unroll
    for (int j = 0; j < 4; j++)
        smt[ty + 8*j][tx] = x[(LL)(r0 + ty + 8*j) * C + c0 + tx];
    __syncthreads();
    #pragma unroll
    for (int j = 0; j < 4; j++) {
        float v = smt[tx][ty + 8*j];
        bf16 h, l; splitw(v, h, l);
        LL o = (LL)(c0 + ty + 8*j) * R + r0 + tx;
        hi[o] = h; lo[o] = l;
    }
}

// ---------------- rmsnorm (fp32 out, kr only) ----------------
__global__ __launch_bounds__(256)
void rmsnorm_kernel(const float* __restrict__ x, const float* __restrict__ g,
                    float* __restrict__ y, int dim)
{
    LL base = (LL)blockIdx.x * dim;
    int tid = threadIdx.x;
    float s = 0.0f;
    for (int i = tid; i < dim; i += 256) { float v = x[base + i]; s += v * v; }
    __shared__ float red[256];
    red[tid] = s; __syncthreads();
    for (int st = 128; st > 0; st >>= 1) {
        if (tid < st) red[tid] += red[tid + st];
        __syncthreads();
    }
    float rs = rsqrtf(red[0] / (float)dim + 1e-6f);
    for (int i = tid; i < dim; i += 256)
        y[base + i] = x[base + i] * rs * g[i];
}

// ---------------- pack with RoPE -> bf16 splits (q pre-scaled) ----------------
__global__ __launch_bounds__(256)
void pack_split(const float* __restrict__ qC, const float* __restrict__ qR,
                const float* __restrict__ krn, const float* __restrict__ kC,
                const float* __restrict__ freqs,
                bf16* __restrict__ qfh, bf16* __restrict__ qfl,
                bf16* __restrict__ kfh, bf16* __restrict__ kfl, float scale)
{
    int bs = blockIdx.x;
    int s  = bs & (SEQ - 1);
    LL qfb = (LL)bs * N_HEADS * D_QK;
    int tid = threadIdx.x;

    __shared__ float krs[D_R];
    if (tid < 32) {
        int i = tid;
        float a = krn[(LL)bs*D_R + 2*i];
        float b = krn[(LL)bs*D_R + 2*i + 1];
        float c  = freqs[(LL)s*D_R + 2*i];
        float sn = freqs[(LL)s*D_R + 2*i + 1];
        krs[2*i]   = a*c - b*sn;
        krs[2*i+1] = a*sn + b*c;
    }
    __syncthreads();

    for (int idx = tid; idx < N_HEADS*D_H; idx += 256) {
        int h = idx >> 7, d = idx & 127;
        float v = qC[(LL)bs*2048 + idx] * scale;
        bf16 hh, ll; splitw(v, hh, ll);
        qfh[qfb + h*D_QK + d] = hh; qfl[qfb + h*D_QK + d] = ll;
    }
    for (int idx = tid; idx < N_HEADS*(D_R/2); idx += 256) {
        int h = idx >> 5, i = idx & 31;
        float a = qR[(LL)bs*1024 + h*D_R + 2*i];
        float b = qR[(LL)bs*1024 + h*D_R + 2*i + 1];
        float c  = freqs[(LL)s*D_R + 2*i];
        float sn = freqs[(LL)s*D_R + 2*i + 1];
        float v0 = (a*c - b*sn) * scale, v1 = (a*sn + b*c) * scale;
        bf16 hh, ll;
        splitw(v0, hh, ll);
        qfh[qfb + h*D_QK + D_H + 2*i] = hh;   qfl[qfb + h*D_QK + D_H + 2*i] = ll;
        splitw(v1, hh, ll);
        qfh[qfb + h*D_QK + D_H + 2*i+1] = hh; qfl[qfb + h*D_QK + D_H + 2*i+1] = ll;
    }
    for (int idx = tid; idx < N_HEADS*D_R; idx += 256) {
        int h = idx >> 6, d = idx & 63;
        bf16 hh, ll; splitw(krs[d], hh, ll);
        kfh[qfb + h*D_QK + d] = hh; kfl[qfb + h*D_QK + d] = ll;
    }
    for (int idx = tid; idx < N_HEADS*D_H; idx += 256) {
        int h = idx >> 7, d = idx & 127;
        float v = kC[(LL)bs*2048 + idx];
        bf16 hh, ll; splitw(v, hh, ll);
        kfh[qfb + h*D_QK + D_R + d] = hh; kfl[qfb + h*D_QK + D_R + d] = ll;
    }
}

// ---------------- causal softmax + bf16 split emission ----------------
__global__ __launch_bounds__(256)
void softmax_kernel(float* __restrict__ w, bf16* __restrict__ wh, bf16* __restrict__ wl)
{
    LL row = blockIdx.x;
    int q = (int)(row & (SEQ - 1));
    float* base = w + row * (LL)SEQ;
    bf16* bh = wh + row * (LL)SEQ;
    bf16* bl = wl + row * (LL)SEQ;
    int tid = threadIdx.x;

    float vals[8];
    float mx = -INFINITY;
    #pragma unroll
    for (int it = 0; it < 8; it++) {
        int k = tid + it * 256;
        float v = -INFINITY;
        if (k <= q) v = base[k];
        vals[it] = v;
        mx = fmaxf(mx, v);
    }
    __shared__ float red[256];
    red[tid] = mx; __syncthreads();
    for (int st = 128; st > 0; st >>= 1) {
        if (tid < st) red[tid] = fmaxf(red[tid], red[tid + st]);
        __syncthreads();
    }
    mx = red[0]; __syncthreads();

    float sum = 0.0f;
    #pragma unroll
    for (int it = 0; it < 8; it++) {
        float e = (vals[it] == -INFINITY) ? 0.0f : __expf(vals[it] - mx);
        vals[it] = e;
        sum += e;
    }
    red[tid] = sum; __syncthreads();
    for (int st = 128; st > 0; st >>= 1) {
        if (tid < st) red[tid] += red[tid + st];
        __syncthreads();
    }
    float inv = 1.0f / red[0];

    int kLim = ((q >> 7) + 1) << 7;   // covers PV's Keff = m0+128
    #pragma unroll
    for (int it = 0; it < 8; it++) {
        int k = tid + it * 256;
        float p = vals[it] * inv;
        base[k] = p;
        if (k < kLim) {
            bf16 h, l; splitw(p, h, l);
            bh[k] = h; bl[k] = l;
        }
    }
}

// ---------------- scalar SGEMM for the tiny N=64 kr projection ----------------
__global__ __launch_bounds__(256)
void gemm_small(const float* __restrict__ A, const float* __restrict__ Bm,
                const float* __restrict__ bias, float* __restrict__ C,
                int K, int lda, int ldb, int ldc)
{
    int m0 = blockIdx.y * 64;
    int n0 = blockIdx.x * 64;
    __shared__ float sA[16][68];
    __shared__ float sB[16][68];
    int tid = threadIdx.x;
    int ty = tid >> 4, tx = tid & 15;
    float acc[4][4] = {};
    int arow = tid >> 2, ak = (tid & 3) * 4;
    int brow = tid >> 4, bcol = (tid & 15) * 4;

    for (int k0 = 0; k0 < K; k0 += 16) {
        float4 a4 = *(const float4*)(A + (LL)(m0 + arow) * lda + k0 + ak);
        sA[ak+0][arow] = a4.x; sA[ak+1][arow] = a4.y;
        sA[ak+2][arow] = a4.z; sA[ak+3][arow] = a4.w;
        float4 b4 = *(const float4*)(Bm + (LL)(k0 + brow) * ldb + n0 + bcol);
        *(float4*)&sB[brow][bcol] = b4;
        __syncthreads();
        #pragma unroll
        for (int kk = 0; kk < 16; kk++) {
            float af[4], bf[4];
            *(float4*)af = *(const float4*)&sA[kk][ty*4];
            *(float4*)bf = *(const float4*)&sB[kk][tx*4];
            #pragma unroll
            for (int i = 0; i < 4; i++)
                #pragma unroll
                for (int j = 0; j < 4; j++)
                    acc[i][j] = fmaf(af[i], bf[j], acc[i][j]);
        }
        __syncthreads();
    }
    #pragma unroll
    for (int i = 0; i < 4; i++)
        #pragma unroll
        for (int j = 0; j < 4; j++)
            C[(LL)(m0 + ty*4 + i) * ldc + n0 + tx*4 + j] = acc[i][j] + bias[n0 + tx*4 + j];
}

// ---------------- host ----------------
#define SYMF(name) ({ void* p_; cudaGetSymbolAddress(&p_, name); (float*)p_; })
#define SYMB(name) ({ void* p_; cudaGetSymbolAddress(&p_, name); (bf16*)p_; })
#define SYMI(name) ({ void* p_; cudaGetSymbolAddress(&p_, name); (int8_t*)p_; })

#define G128_SMEM 98304
#define I8_SMEM   98304

extern "C" void kernel_launch(void* const* d_in, const int* in_sizes, int n_in,
                              void* d_out, int out_size)
{
    (void)in_sizes; (void)n_in; (void)out_size;
    const float* h       = (const float*)d_in[0];
    const float* freqs   = (const float*)d_in[1];
    const float* Wq_down = (const float*)d_in[3];
    const float* bq_down = (const float*)d_in[4];
    const float* gq_norm = (const float*)d_in[5];
    const float* Wqc     = (const float*)d_in[6];
    const float* bqc     = (const float*)d_in[7];
    const float* Wqr     = (const float*)d_in[8];
    const float* bqr     = (const float*)d_in[9];
    const float* Wkr     = (const float*)d_in[10];
    const float* bkr     = (const float*)d_in[11];
    const float* gkr     = (const float*)d_in[12];
    const float* Wkv     = (const float*)d_in[13];
    const float* bkv     = (const float*)d_in[14];
    const float* gkv     = (const float*)d_in[15];
    const float* Wkc     = (const float*)d_in[16];
    const float* bkc     = (const float*)d_in[17];
    const float* Wvc     = (const float*)d_in[18];
    const float* bvc     = (const float*)d_in[19];
    const float* Wo      = (const float*)d_in[20];
    const float* bo      = (const float*)d_in[21];

    float* out_h = (float*)d_out;
    float* w     = out_h + (LL)NTOK * D_MODEL;

    float* tmp1 = SYMF(g_tmp1); float* tmp2 = SYMF(g_tmp2);
    float* qC = SYMF(g_qC);     float* qR = SYMF(g_qR);
    float* kr = SYMF(g_kr);     float* krn = SYMF(g_krn);
    float* kC = SYMF(g_kC);     float* vC = SYMF(g_vC);
    float* attnf = SYMF(g_attnf);

    int8_t *h1 = SYMI(g_h1), *h2 = SYMI(g_h2);        float* sh = SYMF(g_sh);
    int8_t *Wqd1 = SYMI(g_Wqd1), *Wqd2 = SYMI(g_Wqd2); float* sWqd = SYMF(g_sWqd);
    int8_t *Wqc1 = SYMI(g_Wqc1), *Wqc2 = SYMI(g_Wqc2); float* sWqc = SYMF(g_sWqc);
    int8_t *Wqr1 = SYMI(g_Wqr1), *Wqr2 = SYMI(g_Wqr2); float* sWqr = SYMF(g_sWqr);
    int8_t *Wkv1 = SYMI(g_Wkv1), *Wkv2 = SYMI(g_Wkv2); float* sWkv = SYMF(g_sWkv);
    int8_t *Wkc1 = SYMI(g_Wkc1), *Wkc2 = SYMI(g_Wkc2); float* sWkc = SYMF(g_sWkc);
    int8_t *Wvc1 = SYMI(g_Wvc1), *Wvc2 = SYMI(g_Wvc2); float* sWvc = SYMF(g_sWvc);
    int8_t *Wo1 = SYMI(g_Wo1),   *Wo2 = SYMI(g_Wo2);   float* sWo = SYMF(g_sWo);
    int8_t *cQ1 = SYMI(g_cQ1),   *cQ2 = SYMI(g_cQ2);   float* scQ = SYMF(g_scQ);
    int8_t *cKV1 = SYMI(g_cKV1), *cKV2 = SYMI(g_cKV2); float* scKV = SYMF(g_scKV);
    int8_t *at1 = SYMI(g_at1),   *at2 = SYMI(g_at2);   float* sat = SYMF(g_sat);

    bf16 *qf_hi = SYMB(g_qf_hi), *qf_lo = SYMB(g_qf_lo);
    bf16 *kf_hi = SYMB(g_kf_hi), *kf_lo = SYMB(g_kf_lo);
    bf16 *vCT_hi = SYMB(g_vCT_hi), *vCT_lo = SYMB(g_vCT_lo);
    bf16 *w_hi = SYMB(g_w_hi), *w_lo = SYMB(g_w_lo);

    cudaFuncSetAttribute(gemm_i8, cudaFuncAttributeMaxDynamicSharedMemorySize, I8_SMEM);
    cudaFuncSetAttribute((const void*)gemm128<1,true,false>, cudaFuncAttributeMaxDynamicSharedMemorySize, G128_SMEM);
    cudaFuncSetAttribute((const void*)gemm128<1,false,true>, cudaFuncAttributeMaxDynamicSharedMemorySize, G128_SMEM);

    // L1: quantize h
    quant_rows<<<NTOK, 256>>>(h, h1, h2, sh, D_MODEL);
    // L2-L3: Wq_down quant
    colmax2<<<D_CQ/32, 256>>>(Wq_down, sWqd, D_MODEL, D_CQ);
    quant_tr<<<dim3(D_CQ/32, D_MODEL/32), 256>>>(Wq_down, sWqd, Wqd1, Wqd2, D_MODEL, D_CQ);
    // L4 (PROFILED): tmp1 = h @ Wq_down + b
    gemm_i8<<<dim3(D_CQ/128, NTOK/128), 512, I8_SMEM>>>(
        h1, h2, Wqd1, Wqd2, sh, sWqd, bq_down, tmp1, D_MODEL, D_CQ);

    // remaining weight quants
    colmax2<<<D_C/32, 256>>>(Wkv, sWkv, D_MODEL, D_C);
    quant_tr<<<dim3(D_C/32, D_MODEL/32), 256>>>(Wkv, sWkv, Wkv1, Wkv2, D_MODEL, D_C);
    colmax2<<<2048/32, 256>>>(Wqc, sWqc, D_CQ, 2048);
    quant_tr<<<dim3(2048/32, D_CQ/32), 256>>>(Wqc, sWqc, Wqc1, Wqc2, D_CQ, 2048);
    colmax2<<<1024/32, 256>>>(Wqr, sWqr, D_CQ, 1024);
    quant_tr<<<dim3(1024/32, D_CQ/32), 256>>>(Wqr, sWqr, Wqr1, Wqr2, D_CQ, 1024);
    colmax2<<<2048/32, 256>>>(Wkc, sWkc, D_C, 2048);
    quant_tr<<<dim3(2048/32, D_C/32), 256>>>(Wkc, sWkc, Wkc1, Wkc2, D_C, 2048);
    colmax2<<<2048/32, 256>>>(Wvc, sWvc, D_C, 2048);
    quant_tr<<<dim3(2048/32, D_C/32), 256>>>(Wvc, sWvc, Wvc1, Wvc2, D_C, 2048);
    colmax2<<<2048/32, 256>>>(Wo, sWo, 2048, 2048);
    quant_tr<<<dim3(2048/32, 2048/32), 256>>>(Wo, sWo, Wo1, Wo2, 2048, 2048);

    // cQ = rmsnorm(tmp1) -> int8 slices
    rmsnorm_quant<<<NTOK, 256>>>(tmp1, gq_norm, cQ1, cQ2, scQ, D_CQ);

    // qC, qR
    gemm_i8<<<dim3(2048/128, NTOK/128), 512, I8_SMEM>>>(
        cQ1, cQ2, Wqc1, Wqc2, scQ, sWqc, bqc, qC, D_CQ, 2048);
    gemm_i8<<<dim3(1024/128, NTOK/128), 512, I8_SMEM>>>(
        cQ1, cQ2, Wqr1, Wqr2, scQ, sWqr, bqr, qR, D_CQ, 1024);

    // kr (scalar) + rmsnorm
    gemm_small<<<dim3(1, NTOK/64), 256>>>(h, Wkr, bkr, kr, D_MODEL, D_MODEL, D_R, D_R);
    rmsnorm_kernel<<<NTOK, 256>>>(kr, gkr, krn, D_R);

    // cKV
    gemm_i8<<<dim3(D_C/128, NTOK/128), 512, I8_SMEM>>>(
        h1, h2, Wkv1, Wkv2, sh, sWkv, bkv, tmp2, D_MODEL, D_C);
    rmsnorm_quant<<<NTOK, 256>>>(tmp2, gkv, cKV1, cKV2, scKV, D_C);

    // kC, vC
    gemm_i8<<<dim3(2048/128, NTOK/128), 512, I8_SMEM>>>(
        cKV1, cKV2, Wkc1, Wkc2, scKV, sWkc, bkc, kC, D_C, 2048);
    gemm_i8<<<dim3(2048/128, NTOK/128), 512, I8_SMEM>>>(
        cKV1, cKV2, Wvc1, Wvc2, scKV, sWvc, bvc, vC, D_C, 2048);
    split_tr<<<dim3(2048/32, NTOK/32), 256>>>(vC, vCT_hi, vCT_lo, NTOK, 2048);

    // pack + RoPE (q pre-scaled)
    pack_split<<<NTOK, 256>>>(qC, qR, krn, kC, freqs, qf_hi, qf_lo, kf_hi, kf_lo,
                              1.0f / sqrtf((float)D_QK));

    // scores = q k^T (causal tiles)
    {
        LL soQK = (LL)SEQ * N_HEADS * D_QK, siQK = D_QK;
        LL soW  = (LL)N_HEADS * SEQ * SEQ,  siW  = (LL)SEQ * SEQ;
        gemm128<1,true,false><<<dim3(SEQ/128, SEQ/128, BSZ*N_HEADS), 256, G128_SMEM>>>(
            qf_hi, qf_lo, kf_hi, kf_lo, w, nullptr, nullptr,
            D_QK, N_HEADS*D_QK, N_HEADS*D_QK, SEQ,
            soQK, siQK, soQK, siQK, soW, siW, N_HEADS);
    }

    // softmax
    softmax_kernel<<<(LL)BSZ*N_HEADS*SEQ, 256>>>(w, w_hi, w_lo);

    // PV: attnf = w @ vC (K clipped), fp32 out
    {
        LL soW = (LL)N_HEADS * SEQ * SEQ, siW = (LL)SEQ * SEQ;
        LL soB = 2048;
        LL siB = (LL)D_H * NTOK;
        LL soC = (LL)SEQ * 2048, siC = D_H;
        gemm128<1,false,true><<<dim3(D_H/128, SEQ/128, BSZ*N_HEADS), 256, G128_SMEM>>>(
            w_hi, w_lo, vCT_hi, vCT_lo, attnf, nullptr, nullptr,
            SEQ, SEQ, NTOK, 2048,
            soW, siW, soB, siB, soC, siC, N_HEADS);
    }

    // quantize attn, then h_out = attn @ Wo + bo
    quant_rows<<<NTOK, 256>>>(attnf, at1, at2, sat, 2048);
    gemm_i8<<<dim3(2048/128, NTOK/128), 512, I8_SMEM>>>(
        at1, at2, Wo1, Wo2, sat, sWo, bo, out_h, 2048, 2048);
}

// round 9
// speedup vs baseline: 2.1614x; 2.1614x over previous
#include <cuda_runtime.h>
#include <cuda_bf16.h>
#include <math.h>
#include <stdint.h>

#define D_MODEL 2048
#define N_HEADS 16
#define D_CQ    1536
#define D_C     512
#define D_H     128
#define D_R     64
#define BSZ     4
#define SEQ     2048
#define NTOK    (BSZ*SEQ)
#define D_QK    (D_H + D_R)
#define LL long long

#define SW128(o) ((o) ^ (((o) >> 3) & 0x70))
#define SW64(o)  ((o) ^ (((o) >> 2) & 0x30))

typedef __nv_bfloat16 bf16;

// ---------------- scratch ----------------
__device__ float g_tmp1[(LL)NTOK * D_CQ];
__device__ float g_tmp2[(LL)NTOK * D_C];
__device__ float g_qC  [(LL)NTOK * 2048];
__device__ float g_qR  [(LL)NTOK * 1024];
__device__ float g_kr  [(LL)NTOK * D_R];
__device__ float g_krn [(LL)NTOK * D_R];
__device__ float g_kC  [(LL)NTOK * 2048];
__device__ float g_vC  [(LL)NTOK * 2048];
__device__ bf16 g_h_hi[(LL)NTOK * D_MODEL],        g_h_lo[(LL)NTOK * D_MODEL];
__device__ bf16 g_WqdT_hi[(LL)D_CQ * D_MODEL],     g_WqdT_lo[(LL)D_CQ * D_MODEL];
__device__ bf16 g_WqcT_hi[(LL)2048 * D_CQ],        g_WqcT_lo[(LL)2048 * D_CQ];
__device__ bf16 g_WqrT_hi[(LL)1024 * D_CQ],        g_WqrT_lo[(LL)1024 * D_CQ];
__device__ bf16 g_WkvT_hi[(LL)D_C * D_MODEL],      g_WkvT_lo[(LL)D_C * D_MODEL];
__device__ bf16 g_WkcT_hi[(LL)2048 * D_C],         g_WkcT_lo[(LL)2048 * D_C];
__device__ bf16 g_WvcT_hi[(LL)2048 * D_C],         g_WvcT_lo[(LL)2048 * D_C];
__device__ bf16 g_WoT_hi[(LL)2048 * 2048],         g_WoT_lo[(LL)2048 * 2048];
__device__ bf16 g_cQ_hi[(LL)NTOK * D_CQ],          g_cQ_lo[(LL)NTOK * D_CQ];
__device__ bf16 g_cKV_hi[(LL)NTOK * D_C],          g_cKV_lo[(LL)NTOK * D_C];
__device__ bf16 g_qf_hi[(LL)NTOK * N_HEADS*D_QK],  g_qf_lo[(LL)NTOK * N_HEADS*D_QK];
__device__ bf16 g_kf_hi[(LL)NTOK * N_HEADS*D_QK],  g_kf_lo[(LL)NTOK * N_HEADS*D_QK];
__device__ bf16 g_vCT_hi[(LL)2048 * NTOK],         g_vCT_lo[(LL)2048 * NTOK];
__device__ bf16 g_w_hi[(LL)BSZ*N_HEADS*SEQ*SEQ],   g_w_lo[(LL)BSZ*N_HEADS*SEQ*SEQ];
__device__ bf16 g_attn_hi[(LL)NTOK * 2048],        g_attn_lo[(LL)NTOK * 2048];

// ---------------- helpers ----------------
__device__ __forceinline__ uint32_t smem_u32(const void* p) {
    uint32_t a;
    asm("{ .reg .u64 t; cvta.to.shared.u64 t, %1; cvt.u32.u64 %0, t; }" : "=r"(a) : "l"(p));
    return a;
}
#define CP16(d, s) asm volatile("cp.async.cg.shared.global [%0], [%1], 16;" :: "r"(d), "l"(s))
#define CP_COMMIT() asm volatile("cp.async.commit_group;" ::: "memory")
#define CP_WAIT1() asm volatile("cp.async.wait_group 1;" ::: "memory")
#define CP_WAIT0() asm volatile("cp.async.wait_group 0;" ::: "memory")

__device__ __forceinline__ void ldsm_x4(uint32_t addr, uint32_t& r0, uint32_t& r1,
                                        uint32_t& r2, uint32_t& r3) {
    asm volatile("ldmatrix.sync.aligned.m8n8.x4.shared.b16 {%0,%1,%2,%3}, [%4];"
                 : "=r"(r0), "=r"(r1), "=r"(r2), "=r"(r3) : "r"(addr));
}
__device__ __forceinline__ void mma_bf16(float* c, const uint32_t* a,
                                         uint32_t b0, uint32_t b1) {
    asm volatile(
        "mma.sync.aligned.m16n8k16.row.col.f32.bf16.bf16.f32 "
        "{%0,%1,%2,%3}, {%4,%5,%6,%7}, {%8,%9}, {%0,%1,%2,%3};"
        : "+f"(c[0]), "+f"(c[1]), "+f"(c[2]), "+f"(c[3])
        : "r"(a[0]), "r"(a[1]), "r"(a[2]), "r"(a[3]), "r"(b0), "r"(b1));
}
__device__ __forceinline__ void splitw(float v, bf16& hi, bf16& lo) {
    hi = __float2bfloat16(v);
    lo = __float2bfloat16(v - __bfloat162float(hi));
}

// ============ bf16x3 GEMM: 256x128 tile, 512 threads (16 warps), BK=64, 2-stage ============
// A splits [m][k] (lda), B splits [n][k] (ldb). EPI: 0=fp32+bias, 2=bf16 splits.
// KCLIP: Keff = min(m0+256, K).
template<int EPI, bool KCLIP>
__global__ __launch_bounds__(512, 1)
void gemm512(const bf16* __restrict__ Ahi, const bf16* __restrict__ Alo,
             const bf16* __restrict__ Bhi, const bf16* __restrict__ Blo,
             const float* __restrict__ bias,
             float* __restrict__ C, bf16* __restrict__ Chi, bf16* __restrict__ Clo,
             int K, int lda, int ldb, int ldc,
             LL soA, LL siA, LL soB, LL siB, LL soC, LL siC, int IC)
{
    int m0 = blockIdx.y * 256;
    int n0 = blockIdx.x * 128;

    int z = blockIdx.z;
    LL zo = z / IC, zi = z % IC;
    const bf16* Ah_b = Ahi + zo*soA + zi*siA;
    const bf16* Al_b = Alo + zo*soA + zi*siA;
    const bf16* Bh_b = Bhi + zo*soB + zi*siB;
    const bf16* Bl_b = Blo + zo*soB + zi*siB;

    int Keff = KCLIP ? (m0 + 256 < K ? m0 + 256 : K) : K;
    int KT = Keff >> 6;

    extern __shared__ char sm[];
    uint32_t sb = smem_u32(sm);

    int tid = threadIdx.x;
    int wid = tid >> 5, lane = tid & 31;
    int wm = (wid & 7) << 5;     // 8 warps along m: 32 rows each
    int wn = (wid >> 3) << 6;    // 2 warps along n: 64 cols each
    int g = lane >> 3, r = lane & 7;
    int aro = ((g & 1) << 3) + r, aco = (g >> 1) << 4;
    int bro = ((g >> 1) << 3) + r, bco = (g & 1) << 4;

    float acc[2][8][4];
    #pragma unroll
    for (int i = 0; i < 2; i++)
        #pragma unroll
        for (int j = 0; j < 8; j++)
            #pragma unroll
            for (int t = 0; t < 4; t++) acc[i][j][t] = 0.0f;

    // stage: A_hi 32K | A_lo 32K | B_hi 16K | B_lo 16K = 96K; 2 stages
    #define LOAD_STG(s, k0) do {                                               \
        uint32_t st = sb + (uint32_t)(s) * 98304u;                             \
        _Pragma("unroll")                                                      \
        for (int i = 0; i < 4; i++) {                                          \
            int idx = tid + (i << 9);                                          \
            int row = idx >> 3, c = idx & 7;                                   \
            uint32_t d = st + SW128((uint32_t)((row << 7) + (c << 4)));        \
            LL go = (LL)(m0 + row) * lda + (k0) + (c << 3);                    \
            CP16(d,          Ah_b + go);                                       \
            CP16(d + 32768u, Al_b + go);                                       \
        }                                                                      \
        _Pragma("unroll")                                                      \
        for (int i = 0; i < 2; i++) {                                          \
            int idx = tid + (i << 9);                                          \
            int row = idx >> 3, c = idx & 7;                                   \
            uint32_t d = st + 65536u + SW128((uint32_t)((row << 7) + (c << 4)));\
            LL go = (LL)(n0 + row) * ldb + (k0) + (c << 3);                    \
            CP16(d,          Bh_b + go);                                       \
            CP16(d + 16384u, Bl_b + go);                                       \
        }                                                                      \
    } while (0)

    LOAD_STG(0, 0);
    CP_COMMIT();

    for (int kt = 0; kt < KT; kt++) {
        CP_WAIT0();
        __syncthreads();
        if (kt + 1 < KT) {
            LOAD_STG((kt + 1) & 1, (kt + 1) << 6);
            CP_COMMIT();
        }

        uint32_t aB = sb + (uint32_t)(kt & 1) * 98304u;
        uint32_t bB = aB + 65536u;

        #pragma unroll
        for (int ks = 0; ks < 4; ks++) {
            int kb = ks << 5;
            uint32_t ah[2][4], al[2][4];
            #pragma unroll
            for (int mf = 0; mf < 2; mf++) {
                uint32_t off = SW128((uint32_t)((wm + (mf << 4) + aro) * 128 + kb + aco));
                ldsm_x4(aB + off,          ah[mf][0], ah[mf][1], ah[mf][2], ah[mf][3]);
                ldsm_x4(aB + 32768u + off, al[mf][0], al[mf][1], al[mf][2], al[mf][3]);
            }
            #pragma unroll
            for (int ng = 0; ng < 4; ng++) {
                uint32_t off = SW128((uint32_t)((wn + (ng << 4) + bro) * 128 + kb + bco));
                uint32_t bh0, bh1, bh2, bh3, bl0, bl1, bl2, bl3;
                ldsm_x4(bB + off,          bh0, bh1, bh2, bh3);
                ldsm_x4(bB + 16384u + off, bl0, bl1, bl2, bl3);
                #pragma unroll
                for (int mf = 0; mf < 2; mf++) {
                    float* c0 = acc[mf][(ng << 1)];
                    float* c1 = acc[mf][(ng << 1) + 1];
                    mma_bf16(c0, ah[mf], bh0, bh1);
                    mma_bf16(c1, ah[mf], bh2, bh3);
                    mma_bf16(c0, ah[mf], bl0, bl1);
                    mma_bf16(c1, ah[mf], bl2, bl3);
                    mma_bf16(c0, al[mf], bh0, bh1);
                    mma_bf16(c1, al[mf], bh2, bh3);
                }
            }
        }
    }

    // epilogue
    #pragma unroll
    for (int mf = 0; mf < 2; mf++) {
        int row = m0 + wm + (mf << 4) + (lane >> 2);
        #pragma unroll
        for (int nf = 0; nf < 8; nf++) {
            int col = n0 + wn + (nf << 3) + ((lane & 3) << 1);
            float* a = acc[mf][nf];
            if (EPI == 0) {
                float bx = bias[col], by = bias[col + 1];
                float* Cb = C + zo*soC + zi*siC;
                *(float2*)(Cb + (LL)row * ldc + col)       = make_float2(a[0] + bx, a[1] + by);
                *(float2*)(Cb + (LL)(row + 8) * ldc + col) = make_float2(a[2] + bx, a[3] + by);
            } else {
                bf16* Hb = Chi + zo*soC + zi*siC;
                bf16* Lb = Clo + zo*soC + zi*siC;
                bf16 h0, l0, h1, l1;
                splitw(a[0], h0, l0); splitw(a[1], h1, l1);
                uint32_t hp = ((uint32_t)__bfloat16_as_ushort(h1) << 16) | __bfloat16_as_ushort(h0);
                uint32_t lp = ((uint32_t)__bfloat16_as_ushort(l1) << 16) | __bfloat16_as_ushort(l0);
                *(uint32_t*)(Hb + (LL)row * ldc + col) = hp;
                *(uint32_t*)(Lb + (LL)row * ldc + col) = lp;
                splitw(a[2], h0, l0); splitw(a[3], h1, l1);
                hp = ((uint32_t)__bfloat16_as_ushort(h1) << 16) | __bfloat16_as_ushort(h0);
                lp = ((uint32_t)__bfloat16_as_ushort(l1) << 16) | __bfloat16_as_ushort(l0);
                *(uint32_t*)(Hb + (LL)(row + 8) * ldc + col) = hp;
                *(uint32_t*)(Lb + (LL)(row + 8) * ldc + col) = lp;
            }
        }
    }
}

// ============ score GEMM: bf16x3, 128x128, BK=32, 3-stage, 2 CTAs/SM, causal ============
__global__ __launch_bounds__(256, 2)
void score_gemm(const bf16* __restrict__ Ahi, const bf16* __restrict__ Alo,
                const bf16* __restrict__ Bhi, const bf16* __restrict__ Blo,
                float* __restrict__ W)
{
    int m0 = blockIdx.y * 128;
    int n0 = blockIdx.x * 128;
    if (n0 > m0) return;

    int z = blockIdx.z;
    int b = z >> 4, hh = z & 15;
    const LL lda = (LL)N_HEADS * D_QK;
    LL abase = (LL)b * SEQ * lda + (LL)hh * D_QK;
    const bf16* Ah_b = Ahi + abase;
    const bf16* Al_b = Alo + abase;
    const bf16* Bh_b = Bhi + abase;
    const bf16* Bl_b = Blo + abase;
    float* Wb = W + (LL)z * SEQ * SEQ;

    extern __shared__ char sm[];
    uint32_t sb = smem_u32(sm);

    int tid = threadIdx.x;
    int wid = tid >> 5, lane = tid & 31;
    int wm = (wid & 3) << 5;
    int wn = (wid >> 2) << 6;
    int g = lane >> 3, r = lane & 7;
    int aro = ((g & 1) << 3) + r, aco = (g >> 1) << 4;
    int bro = ((g >> 1) << 3) + r, bco = (g & 1) << 4;

    float acc[2][8][4];
    #pragma unroll
    for (int i = 0; i < 2; i++)
        #pragma unroll
        for (int j = 0; j < 8; j++)
            #pragma unroll
            for (int t = 0; t < 4; t++) acc[i][j][t] = 0.0f;

    #define SLOAD(s, k0) do {                                                  \
        uint32_t st = sb + (uint32_t)(s) * 32768u;                             \
        _Pragma("unroll")                                                      \
        for (int i = 0; i < 2; i++) {                                          \
            int idx = tid + (i << 8);                                          \
            int row = idx >> 2, c = (idx & 3) << 4;                            \
            uint32_t sw = SW64((uint32_t)((row << 6) + c));                    \
            LL goA = (LL)(m0 + row) * lda + (k0) + ((idx & 3) << 3);           \
            LL goB = (LL)(n0 + row) * lda + (k0) + ((idx & 3) << 3);           \
            CP16(st + sw,           Ah_b + goA);                               \
            CP16(st + 8192u  + sw,  Al_b + goA);                               \
            CP16(st + 16384u + sw,  Bh_b + goB);                               \
            CP16(st + 24576u + sw,  Bl_b + goB);                               \
        }                                                                      \
    } while (0)

    const int KT = D_QK / 32;   // 6
    SLOAD(0, 0);  CP_COMMIT();
    SLOAD(1, 32); CP_COMMIT();

    int cs = 0, ls = 2;
    for (int kt = 0; kt < KT; kt++) {
        CP_WAIT1();
        __syncthreads();
        if (kt + 2 < KT) {
            SLOAD(ls, (kt + 2) << 5);
        }
        CP_COMMIT();
        ls++; if (ls == 3) ls = 0;

        uint32_t aB = sb + (uint32_t)cs * 32768u;
        uint32_t bB = aB + 16384u;

        #pragma unroll
        for (int ks = 0; ks < 2; ks++) {
            int kb = ks << 5;
            uint32_t ah[2][4], al[2][4];
            #pragma unroll
            for (int mf = 0; mf < 2; mf++) {
                uint32_t off = SW64((uint32_t)((wm + (mf << 4) + aro) * 64 + kb + aco));
                ldsm_x4(aB + off,         ah[mf][0], ah[mf][1], ah[mf][2], ah[mf][3]);
                ldsm_x4(aB + 8192u + off, al[mf][0], al[mf][1], al[mf][2], al[mf][3]);
            }
            #pragma unroll
            for (int ng = 0; ng < 4; ng++) {
                uint32_t off = SW64((uint32_t)((wn + (ng << 4) + bro) * 64 + kb + bco));
                uint32_t bh0, bh1, bh2, bh3, bl0, bl1, bl2, bl3;
                ldsm_x4(bB + off,         bh0, bh1, bh2, bh3);
                ldsm_x4(bB + 8192u + off, bl0, bl1, bl2, bl3);
                #pragma unroll
                for (int mf = 0; mf < 2; mf++) {
                    float* c0 = acc[mf][(ng << 1)];
                    float* c1 = acc[mf][(ng << 1) + 1];
                    mma_bf16(c0, ah[mf], bh0, bh1);
                    mma_bf16(c1, ah[mf], bh2, bh3);
                    mma_bf16(c0, ah[mf], bl0, bl1);
                    mma_bf16(c1, ah[mf], bl2, bl3);
                    mma_bf16(c0, al[mf], bh0, bh1);
                    mma_bf16(c1, al[mf], bh2, bh3);
                }
            }
        }
        cs++; if (cs == 3) cs = 0;
    }

    #pragma unroll
    for (int mf = 0; mf < 2; mf++) {
        int row = m0 + wm + (mf << 4) + (lane >> 2);
        #pragma unroll
        for (int nf = 0; nf < 8; nf++) {
            int col = n0 + wn + (nf << 3) + ((lane & 3) << 1);
            float* a = acc[mf][nf];
            *(float2*)(Wb + (LL)row * SEQ + col)       = make_float2(a[0], a[1]);
            *(float2*)(Wb + (LL)(row + 8) * SEQ + col) = make_float2(a[2], a[3]);
        }
    }
}

// ---------------- split kernels ----------------
__global__ __launch_bounds__(256)
void split_rm(const float* __restrict__ x, bf16* __restrict__ hi, bf16* __restrict__ lo)
{
    LL base = ((LL)blockIdx.x * 256 + threadIdx.x) * 4;
    float4 v = *(const float4*)(x + base);
    bf16 h[4], l[4];
    splitw(v.x, h[0], l[0]); splitw(v.y, h[1], l[1]);
    splitw(v.z, h[2], l[2]); splitw(v.w, h[3], l[3]);
    *(uint2*)(hi + base) = *(uint2*)h;
    *(uint2*)(lo + base) = *(uint2*)l;
}

__global__ __launch_bounds__(256)
void split_tr(const float* __restrict__ x, bf16* __restrict__ hi, bf16* __restrict__ lo,
              int R, int C)
{
    __shared__ float s[32][33];
    int tx = threadIdx.x & 31, ty = threadIdx.x >> 5;
    int r0 = blockIdx.y * 32, c0 = blockIdx.x * 32;
    #pragma unroll
    for (int j = 0; j < 4; j++)
        s[ty + 8*j][tx] = x[(LL)(r0 + ty + 8*j) * C + c0 + tx];
    __syncthreads();
    #pragma unroll
    for (int j = 0; j < 4; j++) {
        float v = s[tx][ty + 8*j];
        bf16 h, l; splitw(v, h, l);
        LL o = (LL)(c0 + ty + 8*j) * R + r0 + tx;
        hi[o] = h; lo[o] = l;
    }
}

// ---------------- rmsnorm ----------------
__global__ __launch_bounds__(256)
void rmsnorm_kernel(const float* __restrict__ x, const float* __restrict__ g,
                    float* __restrict__ y, int dim)
{
    LL base = (LL)blockIdx.x * dim;
    int tid = threadIdx.x;
    float s = 0.0f;
    for (int i = tid; i < dim; i += 256) { float v = x[base + i]; s += v * v; }
    __shared__ float red[256];
    red[tid] = s; __syncthreads();
    for (int st = 128; st > 0; st >>= 1) {
        if (tid < st) red[tid] += red[tid + st];
        __syncthreads();
    }
    float rs = rsqrtf(red[0] / (float)dim + 1e-6f);
    for (int i = tid; i < dim; i += 256)
        y[base + i] = x[base + i] * rs * g[i];
}

__global__ __launch_bounds__(256)
void rmsnorm_split(const float* __restrict__ x, const float* __restrict__ g,
                   bf16* __restrict__ yh, bf16* __restrict__ yl, int dim)
{
    LL base = (LL)blockIdx.x * dim;
    int tid = threadIdx.x;
    float s = 0.0f;
    for (int i = tid; i < dim; i += 256) { float v = x[base + i]; s += v * v; }
    __shared__ float red[256];
    red[tid] = s; __syncthreads();
    for (int st = 128; st > 0; st >>= 1) {
        if (tid < st) red[tid] += red[tid + st];
        __syncthreads();
    }
    float rs = rsqrtf(red[0] / (float)dim + 1e-6f);
    for (int i = tid; i < dim; i += 256) {
        float v = x[base + i] * rs * g[i];
        bf16 h, l; splitw(v, h, l);
        yh[base + i] = h; yl[base + i] = l;
    }
}

// ---------------- pack with RoPE -> bf16 splits (q pre-scaled) ----------------
__global__ __launch_bounds__(256)
void pack_split(const float* __restrict__ qC, const float* __restrict__ qR,
                const float* __restrict__ krn, const float* __restrict__ kC,
                const float* __restrict__ freqs,
                bf16* __restrict__ qfh, bf16* __restrict__ qfl,
                bf16* __restrict__ kfh, bf16* __restrict__ kfl, float scale)
{
    int bs = blockIdx.x;
    int s  = bs & (SEQ - 1);
    LL qfb = (LL)bs * N_HEADS * D_QK;
    int tid = threadIdx.x;

    __shared__ float krs[D_R];
    if (tid < 32) {
        int i = tid;
        float a = krn[(LL)bs*D_R + 2*i];
        float b = krn[(LL)bs*D_R + 2*i + 1];
        float c  = freqs[(LL)s*D_R + 2*i];
        float sn = freqs[(LL)s*D_R + 2*i + 1];
        krs[2*i]   = a*c - b*sn;
        krs[2*i+1] = a*sn + b*c;
    }
    __syncthreads();

    for (int idx = tid; idx < N_HEADS*D_H; idx += 256) {
        int h = idx >> 7, d = idx & 127;
        float v = qC[(LL)bs*2048 + idx] * scale;
        bf16 hh, ll; splitw(v, hh, ll);
        qfh[qfb + h*D_QK + d] = hh; qfl[qfb + h*D_QK + d] = ll;
    }
    for (int idx = tid; idx < N_HEADS*(D_R/2); idx += 256) {
        int h = idx >> 5, i = idx & 31;
        float a = qR[(LL)bs*1024 + h*D_R + 2*i];
        float b = qR[(LL)bs*1024 + h*D_R + 2*i + 1];
        float c  = freqs[(LL)s*D_R + 2*i];
        float sn = freqs[(LL)s*D_R + 2*i + 1];
        float v0 = (a*c - b*sn) * scale, v1 = (a*sn + b*c) * scale;
        bf16 hh, ll;
        splitw(v0, hh, ll);
        qfh[qfb + h*D_QK + D_H + 2*i] = hh;   qfl[qfb + h*D_QK + D_H + 2*i] = ll;
        splitw(v1, hh, ll);
        qfh[qfb + h*D_QK + D_H + 2*i+1] = hh; qfl[qfb + h*D_QK + D_H + 2*i+1] = ll;
    }
    for (int idx = tid; idx < N_HEADS*D_R; idx += 256) {
        int h = idx >> 6, d = idx & 63;
        bf16 hh, ll; splitw(krs[d], hh, ll);
        kfh[qfb + h*D_QK + d] = hh; kfl[qfb + h*D_QK + d] = ll;
    }
    for (int idx = tid; idx < N_HEADS*D_H; idx += 256) {
        int h = idx >> 7, d = idx & 127;
        float v = kC[(LL)bs*2048 + idx];
        bf16 hh, ll; splitw(v, hh, ll);
        kfh[qfb + h*D_QK + D_R + d] = hh; kfl[qfb + h*D_QK + D_R + d] = ll;
    }
}

// ---------------- causal softmax + bf16 split emission ----------------
__global__ __launch_bounds__(256)
void softmax_kernel(float* __restrict__ w, bf16* __restrict__ wh, bf16* __restrict__ wl)
{
    LL row = blockIdx.x;
    int q = (int)(row & (SEQ - 1));
    float* base = w + row * (LL)SEQ;
    bf16* bh = wh + row * (LL)SEQ;
    bf16* bl = wl + row * (LL)SEQ;
    int tid = threadIdx.x;

    float vals[8];
    float mx = -INFINITY;
    #pragma unroll
    for (int it = 0; it < 8; it++) {
        int k = tid + it * 256;
        float v = -INFINITY;
        if (k <= q) v = base[k];
        vals[it] = v;
        mx = fmaxf(mx, v);
    }
    __shared__ float red[256];
    red[tid] = mx; __syncthreads();
    for (int st = 128; st > 0; st >>= 1) {
        if (tid < st) red[tid] = fmaxf(red[tid], red[tid + st]);
        __syncthreads();
    }
    mx = red[0]; __syncthreads();

    float sum = 0.0f;
    #pragma unroll
    for (int it = 0; it < 8; it++) {
        float e = (vals[it] == -INFINITY) ? 0.0f : __expf(vals[it] - mx);
        vals[it] = e;
        sum += e;
    }
    red[tid] = sum; __syncthreads();
    for (int st = 128; st > 0; st >>= 1) {
        if (tid < st) red[tid] += red[tid + st];
        __syncthreads();
    }
    float inv = 1.0f / red[0];

    int kLim = ((q >> 8) + 1) << 8;   // covers PV's Keff = m0+256
    #pragma unroll
    for (int it = 0; it < 8; it++) {
        int k = tid + it * 256;
        float p = vals[it] * inv;
        base[k] = p;
        if (k < kLim) {
            bf16 h, l; splitw(p, h, l);
            bh[k] = h; bl[k] = l;
        }
    }
}

// ---------------- scalar SGEMM for the tiny N=64 kr projection ----------------
__global__ __launch_bounds__(256)
void gemm_small(const float* __restrict__ A, const float* __restrict__ Bm,
                const float* __restrict__ bias, float* __restrict__ C,
                int K, int lda, int ldb, int ldc)
{
    int m0 = blockIdx.y * 64;
    int n0 = blockIdx.x * 64;
    __shared__ float sA[16][68];
    __shared__ float sB[16][68];
    int tid = threadIdx.x;
    int ty = tid >> 4, tx = tid & 15;
    float acc[4][4] = {};
    int arow = tid >> 2, ak = (tid & 3) * 4;
    int brow = tid >> 4, bcol = (tid & 15) * 4;

    for (int k0 = 0; k0 < K; k0 += 16) {
        float4 a4 = *(const float4*)(A + (LL)(m0 + arow) * lda + k0 + ak);
        sA[ak+0][arow] = a4.x; sA[ak+1][arow] = a4.y;
        sA[ak+2][arow] = a4.z; sA[ak+3][arow] = a4.w;
        float4 b4 = *(const float4*)(Bm + (LL)(k0 + brow) * ldb + n0 + bcol);
        *(float4*)&sB[brow][bcol] = b4;
        __syncthreads();
        #pragma unroll
        for (int kk = 0; kk < 16; kk++) {
            float af[4], bf[4];
            *(float4*)af = *(const float4*)&sA[kk][ty*4];
            *(float4*)bf = *(const float4*)&sB[kk][tx*4];
            #pragma unroll
            for (int i = 0; i < 4; i++)
                #pragma unroll
                for (int j = 0; j < 4; j++)
                    acc[i][j] = fmaf(af[i], bf[j], acc[i][j]);
        }
        __syncthreads();
    }
    #pragma unroll
    for (int i = 0; i < 4; i++)
        #pragma unroll
        for (int j = 0; j < 4; j++)
            C[(LL)(m0 + ty*4 + i) * ldc + n0 + tx*4 + j] = acc[i][j] + bias[n0 + tx*4 + j];
}

// ---------------- host ----------------
#define SYMF(name) ({ void* p_; cudaGetSymbolAddress(&p_, name); (float*)p_; })
#define SYMB(name) ({ void* p_; cudaGetSymbolAddress(&p_, name); (bf16*)p_; })

#define G512_SMEM  196608
#define SCORE_SMEM 98304

extern "C" void kernel_launch(void* const* d_in, const int* in_sizes, int n_in,
                              void* d_out, int out_size)
{
    (void)in_sizes; (void)n_in; (void)out_size;
    const float* h       = (const float*)d_in[0];
    const float* freqs   = (const float*)d_in[1];
    const float* Wq_down = (const float*)d_in[3];
    const float* bq_down = (const float*)d_in[4];
    const float* gq_norm = (const float*)d_in[5];
    const float* Wqc     = (const float*)d_in[6];
    const float* bqc     = (const float*)d_in[7];
    const float* Wqr     = (const float*)d_in[8];
    const float* bqr     = (const float*)d_in[9];
    const float* Wkr     = (const float*)d_in[10];
    const float* bkr     = (const float*)d_in[11];
    const float* gkr     = (const float*)d_in[12];
    const float* Wkv     = (const float*)d_in[13];
    const float* bkv     = (const float*)d_in[14];
    const float* gkv     = (const float*)d_in[15];
    const float* Wkc     = (const float*)d_in[16];
    const float* bkc     = (const float*)d_in[17];
    const float* Wvc     = (const float*)d_in[18];
    const float* bvc     = (const float*)d_in[19];
    const float* Wo      = (const float*)d_in[20];
    const float* bo      = (const float*)d_in[21];

    float* out_h = (float*)d_out;
    float* w     = out_h + (LL)NTOK * D_MODEL;

    float* tmp1 = SYMF(g_tmp1); float* tmp2 = SYMF(g_tmp2);
    float* qC = SYMF(g_qC);     float* qR = SYMF(g_qR);
    float* kr = SYMF(g_kr);     float* krn = SYMF(g_krn);
    float* kC = SYMF(g_kC);     float* vC = SYMF(g_vC);

    bf16 *h_hi = SYMB(g_h_hi), *h_lo = SYMB(g_h_lo);
    bf16 *WqdT_hi = SYMB(g_WqdT_hi), *WqdT_lo = SYMB(g_WqdT_lo);
    bf16 *WqcT_hi = SYMB(g_WqcT_hi), *WqcT_lo = SYMB(g_WqcT_lo);
    bf16 *WqrT_hi = SYMB(g_WqrT_hi), *WqrT_lo = SYMB(g_WqrT_lo);
    bf16 *WkvT_hi = SYMB(g_WkvT_hi), *WkvT_lo = SYMB(g_WkvT_lo);
    bf16 *WkcT_hi = SYMB(g_WkcT_hi), *WkcT_lo = SYMB(g_WkcT_lo);
    bf16 *WvcT_hi = SYMB(g_WvcT_hi), *WvcT_lo = SYMB(g_WvcT_lo);
    bf16 *WoT_hi  = SYMB(g_WoT_hi),  *WoT_lo  = SYMB(g_WoT_lo);
    bf16 *cQ_hi = SYMB(g_cQ_hi), *cQ_lo = SYMB(g_cQ_lo);
    bf16 *cKV_hi = SYMB(g_cKV_hi), *cKV_lo = SYMB(g_cKV_lo);
    bf16 *qf_hi = SYMB(g_qf_hi), *qf_lo = SYMB(g_qf_lo);
    bf16 *kf_hi = SYMB(g_kf_hi), *kf_lo = SYMB(g_kf_lo);
    bf16 *vCT_hi = SYMB(g_vCT_hi), *vCT_lo = SYMB(g_vCT_lo);
    bf16 *w_hi = SYMB(g_w_hi), *w_lo = SYMB(g_w_lo);
    bf16 *attn_hi = SYMB(g_attn_hi), *attn_lo = SYMB(g_attn_lo);

    cudaFuncSetAttribute((const void*)gemm512<0,false>, cudaFuncAttributeMaxDynamicSharedMemorySize, G512_SMEM);
    cudaFuncSetAttribute((const void*)gemm512<2,true>,  cudaFuncAttributeMaxDynamicSharedMemorySize, G512_SMEM);
    cudaFuncSetAttribute(score_gemm, cudaFuncAttributeMaxDynamicSharedMemorySize, SCORE_SMEM);

    // L1: split h
    split_rm<<<(LL)NTOK*D_MODEL/1024, 256>>>(h, h_hi, h_lo);
    // L2: split Wq_down^T
    split_tr<<<dim3(D_CQ/32, D_MODEL/32), 256>>>(Wq_down, WqdT_hi, WqdT_lo, D_MODEL, D_CQ);
    // L3: split Wkv^T
    split_tr<<<dim3(D_C/32, D_MODEL/32), 256>>>(Wkv, WkvT_hi, WkvT_lo, D_MODEL, D_C);
    // L4 (PROFILED): tmp1 = h @ Wq_down + b
    gemm512<0,false><<<dim3(D_CQ/128, NTOK/256), 512, G512_SMEM>>>(
        h_hi, h_lo, WqdT_hi, WqdT_lo, bq_down, tmp1, nullptr, nullptr,
        D_MODEL, D_MODEL, D_MODEL, D_CQ, 0,0,0,0,0,0,1);

    // remaining weight splits
    split_tr<<<dim3(2048/32, D_CQ/32), 256>>>(Wqc, WqcT_hi, WqcT_lo, D_CQ, 2048);
    split_tr<<<dim3(1024/32, D_CQ/32), 256>>>(Wqr, WqrT_hi, WqrT_lo, D_CQ, 1024);
    split_tr<<<dim3(2048/32, D_C/32), 256>>>(Wkc, WkcT_hi, WkcT_lo, D_C, 2048);
    split_tr<<<dim3(2048/32, D_C/32), 256>>>(Wvc, WvcT_hi, WvcT_lo, D_C, 2048);
    split_tr<<<dim3(2048/32, 2048/32), 256>>>(Wo, WoT_hi, WoT_lo, 2048, 2048);

    // cQ = rmsnorm(tmp1) -> bf16 splits
    rmsnorm_split<<<NTOK, 256>>>(tmp1, gq_norm, cQ_hi, cQ_lo, D_CQ);

    // qC, qR
    gemm512<0,false><<<dim3(2048/128, NTOK/256), 512, G512_SMEM>>>(
        cQ_hi, cQ_lo, WqcT_hi, WqcT_lo, bqc, qC, nullptr, nullptr,
        D_CQ, D_CQ, D_CQ, 2048, 0,0,0,0,0,0,1);
    gemm512<0,false><<<dim3(1024/128, NTOK/256), 512, G512_SMEM>>>(
        cQ_hi, cQ_lo, WqrT_hi, WqrT_lo, bqr, qR, nullptr, nullptr,
        D_CQ, D_CQ, D_CQ, 1024, 0,0,0,0,0,0,1);

    // kr (scalar) + rmsnorm
    gemm_small<<<dim3(1, NTOK/64), 256>>>(h, Wkr, bkr, kr, D_MODEL, D_MODEL, D_R, D_R);
    rmsnorm_kernel<<<NTOK, 256>>>(kr, gkr, krn, D_R);

    // cKV
    gemm512<0,false><<<dim3(D_C/128, NTOK/256), 512, G512_SMEM>>>(
        h_hi, h_lo, WkvT_hi, WkvT_lo, bkv, tmp2, nullptr, nullptr,
        D_MODEL, D_MODEL, D_MODEL, D_C, 0,0,0,0,0,0,1);
    rmsnorm_split<<<NTOK, 256>>>(tmp2, gkv, cKV_hi, cKV_lo, D_C);

    // kC, vC
    gemm512<0,false><<<dim3(2048/128, NTOK/256), 512, G512_SMEM>>>(
        cKV_hi, cKV_lo, WkcT_hi, WkcT_lo, bkc, kC, nullptr, nullptr,
        D_C, D_C, D_C, 2048, 0,0,0,0,0,0,1);
    gemm512<0,false><<<dim3(2048/128, NTOK/256), 512, G512_SMEM>>>(
        cKV_hi, cKV_lo, WvcT_hi, WvcT_lo, bvc, vC, nullptr, nullptr,
        D_C, D_C, D_C, 2048, 0,0,0,0,0,0,1);
    split_tr<<<dim3(2048/32, NTOK/32), 256>>>(vC, vCT_hi, vCT_lo, NTOK, 2048);

    // pack + RoPE (q pre-scaled)
    pack_split<<<NTOK, 256>>>(qC, qR, krn, kC, freqs, qf_hi, qf_lo, kf_hi, kf_lo,
                              1.0f / sqrtf((float)D_QK));

    // scores = q k^T (causal tiles, 2 CTAs/SM)
    score_gemm<<<dim3(SEQ/128, SEQ/128, BSZ*N_HEADS), 256, SCORE_SMEM>>>(
        qf_hi, qf_lo, kf_hi, kf_lo, w);

    // softmax
    softmax_kernel<<<(LL)BSZ*N_HEADS*SEQ, 256>>>(w, w_hi, w_lo);

    // PV: attn = w @ vC (K clipped at diagonal), bf16-split output
    {
        LL soW = (LL)N_HEADS * SEQ * SEQ, siW = (LL)SEQ * SEQ;
        LL soB = 2048;
        LL siB = (LL)D_H * NTOK;
        LL soC = (LL)SEQ * 2048, siC = D_H;
        gemm512<2,true><<<dim3(D_H/128, SEQ/256, BSZ*N_HEADS), 512, G512_SMEM>>>(
            w_hi, w_lo, vCT_hi, vCT_lo, nullptr, nullptr, attn_hi, attn_lo,
            SEQ, SEQ, NTOK, 2048,
            soW, siW, soB, siB, soC, siC, N_HEADS);
    }

    // h_out = attn @ Wo + bo
    gemm512<0,false><<<dim3(2048/128, NTOK/256), 512, G512_SMEM>>>(
        attn_hi, attn_lo, WoT_hi, WoT_lo, bo, out_h, nullptr, nullptr,
        2048, 2048, 2048, 2048, 0,0,0,0,0,0,1);
}

// round 10
// speedup vs baseline: 2.1828x; 1.0099x over previous
#include <cuda_runtime.h>
#include <cuda_bf16.h>
#include <math.h>
#include <stdint.h>

#define D_MODEL 2048
#define N_HEADS 16
#define D_CQ    1536
#define D_C     512
#define D_H     128
#define D_R     64
#define BSZ     4
#define SEQ     2048
#define NTOK    (BSZ*SEQ)
#define D_QK    (D_H + D_R)
#define LL long long

#define SW128(o) ((o) ^ (((o) >> 3) & 0x70))
#define SW64(o)  ((o) ^ (((o) >> 2) & 0x30))

typedef __nv_bfloat16 bf16;

// ---------------- scratch ----------------
__device__ float g_tmp12[(LL)NTOK * 2048];          // [cQpre | cKVpre]
__device__ float g_qCR [(LL)NTOK * 3072];           // [qC | qR]
__device__ float g_kvC [(LL)NTOK * 4096];           // [kC | vC]
__device__ float g_kr  [(LL)NTOK * D_R];
__device__ float g_krn [(LL)NTOK * D_R];
__device__ bf16 g_h_hi[(LL)NTOK * D_MODEL],      g_h_lo[(LL)NTOK * D_MODEL];
__device__ bf16 g_WdT_hi[(LL)2048 * D_MODEL],    g_WdT_lo[(LL)2048 * D_MODEL];    // [WqdT | WkvT] rows
__device__ bf16 g_WqcrT_hi[(LL)3072 * D_CQ],     g_WqcrT_lo[(LL)3072 * D_CQ];     // [WqcT | WqrT]
__device__ bf16 g_WkvcT_hi[(LL)4096 * D_C],      g_WkvcT_lo[(LL)4096 * D_C];      // [WkcT | WvcT]
__device__ bf16 g_WoT_hi[(LL)2048 * 2048],       g_WoT_lo[(LL)2048 * 2048];
__device__ bf16 g_cQ_hi[(LL)NTOK * D_CQ],        g_cQ_lo[(LL)NTOK * D_CQ];
__device__ bf16 g_cKV_hi[(LL)NTOK * D_C],        g_cKV_lo[(LL)NTOK * D_C];
__device__ bf16 g_qf_hi[(LL)NTOK * N_HEADS*D_QK], g_qf_lo[(LL)NTOK * N_HEADS*D_QK];
__device__ bf16 g_kf_hi[(LL)NTOK * N_HEADS*D_QK], g_kf_lo[(LL)NTOK * N_HEADS*D_QK];
__device__ bf16 g_vCT_hi[(LL)2048 * NTOK],       g_vCT_lo[(LL)2048 * NTOK];
__device__ bf16 g_w_hi[(LL)BSZ*N_HEADS*SEQ*SEQ], g_w_lo[(LL)BSZ*N_HEADS*SEQ*SEQ];
__device__ bf16 g_attn_hi[(LL)NTOK * 2048],      g_attn_lo[(LL)NTOK * 2048];
__device__ float g_bias1[2048];   // [bq_down | bkv]
__device__ float g_bias2[3072];   // [bqc | bqr]
__device__ float g_bias3[4096];   // [bkc | bvc]

// ---------------- helpers ----------------
__device__ __forceinline__ uint32_t smem_u32(const void* p) {
    uint32_t a;
    asm("{ .reg .u64 t; cvta.to.shared.u64 t, %1; cvt.u32.u64 %0, t; }" : "=r"(a) : "l"(p));
    return a;
}
#define CP16(d, s) asm volatile("cp.async.cg.shared.global [%0], [%1], 16;" :: "r"(d), "l"(s))
#define CP_COMMIT() asm volatile("cp.async.commit_group;" ::: "memory")
#define CP_WAIT1() asm volatile("cp.async.wait_group 1;" ::: "memory")
#define CP_WAIT0() asm volatile("cp.async.wait_group 0;" ::: "memory")

__device__ __forceinline__ void ldsm_x4(uint32_t addr, uint32_t& r0, uint32_t& r1,
                                        uint32_t& r2, uint32_t& r3) {
    asm volatile("ldmatrix.sync.aligned.m8n8.x4.shared.b16 {%0,%1,%2,%3}, [%4];"
                 : "=r"(r0), "=r"(r1), "=r"(r2), "=r"(r3) : "r"(addr));
}
__device__ __forceinline__ void mma_bf16(float* c, const uint32_t* a,
                                         uint32_t b0, uint32_t b1) {
    asm volatile(
        "mma.sync.aligned.m16n8k16.row.col.f32.bf16.bf16.f32 "
        "{%0,%1,%2,%3}, {%4,%5,%6,%7}, {%8,%9}, {%0,%1,%2,%3};"
        : "+f"(c[0]), "+f"(c[1]), "+f"(c[2]), "+f"(c[3])
        : "r"(a[0]), "r"(a[1]), "r"(a[2]), "r"(a[3]), "r"(b0), "r"(b1));
}
__device__ __forceinline__ void splitw(float v, bf16& hi, bf16& lo) {
    hi = __float2bfloat16(v);
    lo = __float2bfloat16(v - __bfloat162float(hi));
}

// ============ bf16x3 GEMM: 256x128 tile, 512 threads, BK=64, 2-stage ============
// EPI: 0=fp32+bias, 2=bf16 splits.  KCLIP: Keff = min(m0+256, K).
template<int EPI, bool KCLIP>
__global__ __launch_bounds__(512, 1)
void gemm512(const bf16* __restrict__ Ahi, const bf16* __restrict__ Alo,
             const bf16* __restrict__ Bhi, const bf16* __restrict__ Blo,
             const float* __restrict__ bias,
             float* __restrict__ C, bf16* __restrict__ Chi, bf16* __restrict__ Clo,
             int K, int lda, int ldb, int ldc,
             LL soA, LL siA, LL soB, LL siB, LL soC, LL siC, int IC)
{
    int m0 = blockIdx.y * 256;
    int n0 = blockIdx.x * 128;

    int z = blockIdx.z;
    LL zo = z / IC, zi = z % IC;
    const bf16* Ah_b = Ahi + zo*soA + zi*siA;
    const bf16* Al_b = Alo + zo*soA + zi*siA;
    const bf16* Bh_b = Bhi + zo*soB + zi*siB;
    const bf16* Bl_b = Blo + zo*soB + zi*siB;

    int Keff = KCLIP ? (m0 + 256 < K ? m0 + 256 : K) : K;
    int KT = Keff >> 6;

    extern __shared__ char sm[];
    uint32_t sb = smem_u32(sm);

    int tid = threadIdx.x;
    int wid = tid >> 5, lane = tid & 31;
    int wm = (wid & 7) << 5;
    int wn = (wid >> 3) << 6;
    int g = lane >> 3, r = lane & 7;
    int aro = ((g & 1) << 3) + r, aco = (g >> 1) << 4;
    int bro = ((g >> 1) << 3) + r, bco = (g & 1) << 4;

    float acc[2][8][4];
    #pragma unroll
    for (int i = 0; i < 2; i++)
        #pragma unroll
        for (int j = 0; j < 8; j++)
            #pragma unroll
            for (int t = 0; t < 4; t++) acc[i][j][t] = 0.0f;

    #define LOAD_STG(s, k0) do {                                               \
        uint32_t st = sb + (uint32_t)(s) * 98304u;                             \
        _Pragma("unroll")                                                      \
        for (int i = 0; i < 4; i++) {                                          \
            int idx = tid + (i << 9);                                          \
            int row = idx >> 3, c = idx & 7;                                   \
            uint32_t d = st + SW128((uint32_t)((row << 7) + (c << 4)));        \
            LL go = (LL)(m0 + row) * lda + (k0) + (c << 3);                    \
            CP16(d,          Ah_b + go);                                       \
            CP16(d + 32768u, Al_b + go);                                       \
        }                                                                      \
        _Pragma("unroll")                                                      \
        for (int i = 0; i < 2; i++) {                                          \
            int idx = tid + (i << 9);                                          \
            int row = idx >> 3, c = idx & 7;                                   \
            uint32_t d = st + 65536u + SW128((uint32_t)((row << 7) + (c << 4)));\
            LL go = (LL)(n0 + row) * ldb + (k0) + (c << 3);                    \
            CP16(d,          Bh_b + go);                                       \
            CP16(d + 16384u, Bl_b + go);                                       \
        }                                                                      \
    } while (0)

    LOAD_STG(0, 0);
    CP_COMMIT();

    for (int kt = 0; kt < KT; kt++) {
        CP_WAIT0();
        __syncthreads();
        if (kt + 1 < KT) {
            LOAD_STG((kt + 1) & 1, (kt + 1) << 6);
            CP_COMMIT();
        }

        uint32_t aB = sb + (uint32_t)(kt & 1) * 98304u;
        uint32_t bB = aB + 65536u;

        #pragma unroll
        for (int ks = 0; ks < 4; ks++) {
            int kb = ks << 5;
            uint32_t ah[2][4], al[2][4];
            #pragma unroll
            for (int mf = 0; mf < 2; mf++) {
                uint32_t off = SW128((uint32_t)((wm + (mf << 4) + aro) * 128 + kb + aco));
                ldsm_x4(aB + off,          ah[mf][0], ah[mf][1], ah[mf][2], ah[mf][3]);
                ldsm_x4(aB + 32768u + off, al[mf][0], al[mf][1], al[mf][2], al[mf][3]);
            }
            #pragma unroll
            for (int ng = 0; ng < 4; ng++) {
                uint32_t off = SW128((uint32_t)((wn + (ng << 4) + bro) * 128 + kb + bco));
                uint32_t bh0, bh1, bh2, bh3, bl0, bl1, bl2, bl3;
                ldsm_x4(bB + off,          bh0, bh1, bh2, bh3);
                ldsm_x4(bB + 16384u + off, bl0, bl1, bl2, bl3);
                #pragma unroll
                for (int mf = 0; mf < 2; mf++) {
                    float* c0 = acc[mf][(ng << 1)];
                    float* c1 = acc[mf][(ng << 1) + 1];
                    mma_bf16(c0, ah[mf], bh0, bh1);
                    mma_bf16(c1, ah[mf], bh2, bh3);
                    mma_bf16(c0, ah[mf], bl0, bl1);
                    mma_bf16(c1, ah[mf], bl2, bl3);
                    mma_bf16(c0, al[mf], bh0, bh1);
                    mma_bf16(c1, al[mf], bh2, bh3);
                }
            }
        }
    }

    #pragma unroll
    for (int mf = 0; mf < 2; mf++) {
        int row = m0 + wm + (mf << 4) + (lane >> 2);
        #pragma unroll
        for (int nf = 0; nf < 8; nf++) {
            int col = n0 + wn + (nf << 3) + ((lane & 3) << 1);
            float* a = acc[mf][nf];
            if (EPI == 0) {
                float bx = bias[col], by = bias[col + 1];
                float* Cb = C + zo*soC + zi*siC;
                *(float2*)(Cb + (LL)row * ldc + col)       = make_float2(a[0] + bx, a[1] + by);
                *(float2*)(Cb + (LL)(row + 8) * ldc + col) = make_float2(a[2] + bx, a[3] + by);
            } else {
                bf16* Hb = Chi + zo*soC + zi*siC;
                bf16* Lb = Clo + zo*soC + zi*siC;
                bf16 h0, l0, h1, l1;
                splitw(a[0], h0, l0); splitw(a[1], h1, l1);
                uint32_t hp = ((uint32_t)__bfloat16_as_ushort(h1) << 16) | __bfloat16_as_ushort(h0);
                uint32_t lp = ((uint32_t)__bfloat16_as_ushort(l1) << 16) | __bfloat16_as_ushort(l0);
                *(uint32_t*)(Hb + (LL)row * ldc + col) = hp;
                *(uint32_t*)(Lb + (LL)row * ldc + col) = lp;
                splitw(a[2], h0, l0); splitw(a[3], h1, l1);
                hp = ((uint32_t)__bfloat16_as_ushort(h1) << 16) | __bfloat16_as_ushort(h0);
                lp = ((uint32_t)__bfloat16_as_ushort(l1) << 16) | __bfloat16_as_ushort(l0);
                *(uint32_t*)(Hb + (LL)(row + 8) * ldc + col) = hp;
                *(uint32_t*)(Lb + (LL)(row + 8) * ldc + col) = lp;
            }
        }
    }
}

// ============ score GEMM: bf16x3, 128x128, BK=32, 3-stage, 2 CTAs/SM, causal ============
__global__ __launch_bounds__(256, 2)
void score_gemm(const bf16* __restrict__ Ahi, const bf16* __restrict__ Alo,
                const bf16* __restrict__ Bhi, const bf16* __restrict__ Blo,
                float* __restrict__ W)
{
    int m0 = blockIdx.y * 128;
    int n0 = blockIdx.x * 128;
    if (n0 > m0) return;

    int z = blockIdx.z;
    int b = z >> 4, hh = z & 15;
    const LL lda = (LL)N_HEADS * D_QK;
    LL abase = (LL)b * SEQ * lda + (LL)hh * D_QK;
    const bf16* Ah_b = Ahi + abase;
    const bf16* Al_b = Alo + abase;
    const bf16* Bh_b = Bhi + abase;
    const bf16* Bl_b = Blo + abase;
    float* Wb = W + (LL)z * SEQ * SEQ;

    extern __shared__ char sm[];
    uint32_t sb = smem_u32(sm);

    int tid = threadIdx.x;
    int wid = tid >> 5, lane = tid & 31;
    int wm = (wid & 3) << 5;
    int wn = (wid >> 2) << 6;
    int g = lane >> 3, r = lane & 7;
    int aro = ((g & 1) << 3) + r, aco = (g >> 1) << 4;
    int bro = ((g >> 1) << 3) + r, bco = (g & 1) << 4;

    float acc[2][8][4];
    #pragma unroll
    for (int i = 0; i < 2; i++)
        #pragma unroll
        for (int j = 0; j < 8; j++)
            #pragma unroll
            for (int t = 0; t < 4; t++) acc[i][j][t] = 0.0f;

    #define SLOAD(s, k0) do {                                                  \
        uint32_t st = sb + (uint32_t)(s) * 32768u;                             \
        _Pragma("unroll")                                                      \
        for (int i = 0; i < 2; i++) {                                          \
            int idx = tid + (i << 8);                                          \
            int row = idx >> 2, c = (idx & 3) << 4;                            \
            uint32_t sw = SW64((uint32_t)((row << 6) + c));                    \
            LL goA = (LL)(m0 + row) * lda + (k0) + ((idx & 3) << 3);           \
            LL goB = (LL)(n0 + row) * lda + (k0) + ((idx & 3) << 3);           \
            CP16(st + sw,           Ah_b + goA);                               \
            CP16(st + 8192u  + sw,  Al_b + goA);                               \
            CP16(st + 16384u + sw,  Bh_b + goB);                               \
            CP16(st + 24576u + sw,  Bl_b + goB);                               \
        }                                                                      \
    } while (0)

    const int KT = D_QK / 32;   // 6
    SLOAD(0, 0);  CP_COMMIT();
    SLOAD(1, 32); CP_COMMIT();

    int cs = 0, ls = 2;
    for (int kt = 0; kt < KT; kt++) {
        CP_WAIT1();
        __syncthreads();
        if (kt + 2 < KT) {
            SLOAD(ls, (kt + 2) << 5);
        }
        CP_COMMIT();
        ls++; if (ls == 3) ls = 0;

        uint32_t aB = sb + (uint32_t)cs * 32768u;
        uint32_t bB = aB + 16384u;

        #pragma unroll
        for (int ks = 0; ks < 2; ks++) {
            int kb = ks << 5;
            uint32_t ah[2][4], al[2][4];
            #pragma unroll
            for (int mf = 0; mf < 2; mf++) {
                uint32_t off = SW64((uint32_t)((wm + (mf << 4) + aro) * 64 + kb + aco));
                ldsm_x4(aB + off,         ah[mf][0], ah[mf][1], ah[mf][2], ah[mf][3]);
                ldsm_x4(aB + 8192u + off, al[mf][0], al[mf][1], al[mf][2], al[mf][3]);
            }
            #pragma unroll
            for (int ng = 0; ng < 4; ng++) {
                uint32_t off = SW64((uint32_t)((wn + (ng << 4) + bro) * 64 + kb + bco));
                uint32_t bh0, bh1, bh2, bh3, bl0, bl1, bl2, bl3;
                ldsm_x4(bB + off,         bh0, bh1, bh2, bh3);
                ldsm_x4(bB + 8192u + off, bl0, bl1, bl2, bl3);
                #pragma unroll
                for (int mf = 0; mf < 2; mf++) {
                    float* c0 = acc[mf][(ng << 1)];
                    float* c1 = acc[mf][(ng << 1) + 1];
                    mma_bf16(c0, ah[mf], bh0, bh1);
                    mma_bf16(c1, ah[mf], bh2, bh3);
                    mma_bf16(c0, ah[mf], bl0, bl1);
                    mma_bf16(c1, ah[mf], bl2, bl3);
                    mma_bf16(c0, al[mf], bh0, bh1);
                    mma_bf16(c1, al[mf], bh2, bh3);
                }
            }
        }
        cs++; if (cs == 3) cs = 0;
    }

    #pragma unroll
    for (int mf = 0; mf < 2; mf++) {
        int row = m0 + wm + (mf << 4) + (lane >> 2);
        #pragma unroll
        for (int nf = 0; nf < 8; nf++) {
            int col = n0 + wn + (nf << 3) + ((lane & 3) << 1);
            float* a = acc[mf][nf];
            *(float2*)(Wb + (LL)row * SEQ + col)       = make_float2(a[0], a[1]);
            *(float2*)(Wb + (LL)(row + 8) * SEQ + col) = make_float2(a[2], a[3]);
        }
    }
}

// ---------------- split kernels ----------------
__global__ __launch_bounds__(256)
void split_rm(const float* __restrict__ x, bf16* __restrict__ hi, bf16* __restrict__ lo)
{
    LL base = ((LL)blockIdx.x * 256 + threadIdx.x) * 4;
    float4 v = *(const float4*)(x + base);
    bf16 h[4], l[4];
    splitw(v.x, h[0], l[0]); splitw(v.y, h[1], l[1]);
    splitw(v.z, h[2], l[2]); splitw(v.w, h[3], l[3]);
    *(uint2*)(hi + base) = *(uint2*)h;
    *(uint2*)(lo + base) = *(uint2*)l;
}

// x[R rows][ldx cols] fp32 (use cols 0..C-1) -> dest[C rows][R cols] bf16 hi/lo
__global__ __launch_bounds__(256)
void split_tr(const float* __restrict__ x, int ldx,
              bf16* __restrict__ hi, bf16* __restrict__ lo, int R, int C)
{
    __shared__ float s[32][33];
    int tx = threadIdx.x & 31, ty = threadIdx.x >> 5;
    int r0 = blockIdx.y * 32, c0 = blockIdx.x * 32;
    #pragma unroll
    for (int j = 0; j < 4; j++)
        s[ty + 8*j][tx] = x[(LL)(r0 + ty + 8*j) * ldx + c0 + tx];
    __syncthreads();
    #pragma unroll
    for (int j = 0; j < 4; j++) {
        float v = s[tx][ty + 8*j];
        bf16 h, l; splitw(v, h, l);
        LL o = (LL)(c0 + ty + 8*j) * R + r0 + tx;
        hi[o] = h; lo[o] = l;
    }
}

// ---------------- bias concat ----------------
__global__ __launch_bounds__(256)
void biascat(const float* __restrict__ bqd, const float* __restrict__ bkv,
             const float* __restrict__ bqc, const float* __restrict__ bqr,
             const float* __restrict__ bkc, const float* __restrict__ bvc,
             float* __restrict__ b1, float* __restrict__ b2, float* __restrict__ b3)
{
    int i = blockIdx.x * 256 + threadIdx.x;
    if (i < 1536) b1[i] = bqd[i]; else if (i < 2048) b1[i] = bkv[i - 1536];
    if (i < 2048) b2[i] = bqc[i]; else if (i < 3072) b2[i] = bqr[i - 2048];
    if (i < 2048) b3[i] = bkc[i]; else b3[i] = bvc[i - 2048];
}

// ---------------- rmsnorm ----------------
__global__ __launch_bounds__(256)
void rmsnorm_kernel(const float* __restrict__ x, const float* __restrict__ g,
                    float* __restrict__ y, int dim)
{
    LL base = (LL)blockIdx.x * dim;
    int tid = threadIdx.x;
    float s = 0.0f;
    for (int i = tid; i < dim; i += 256) { float v = x[base + i]; s += v * v; }
    __shared__ float red[256];
    red[tid] = s; __syncthreads();
    for (int st = 128; st > 0; st >>= 1) {
        if (tid < st) red[tid] += red[tid + st];
        __syncthreads();
    }
    float rs = rsqrtf(red[0] / (float)dim + 1e-6f);
    for (int i = tid; i < dim; i += 256)
        y[base + i] = x[base + i] * rs * g[i];
}

// rmsnorm on a column-slice of x [rows][ldx], cols off..off+dim-1 -> bf16 splits [rows][dim]
__global__ __launch_bounds__(256)
void rmsnorm_split(const float* __restrict__ x, int ldx, int off,
                   const float* __restrict__ g,
                   bf16* __restrict__ yh, bf16* __restrict__ yl, int dim)
{
    LL xb = (LL)blockIdx.x * ldx + off;
    LL yb = (LL)blockIdx.x * dim;
    int tid = threadIdx.x;
    float s = 0.0f;
    for (int i = tid; i < dim; i += 256) { float v = x[xb + i]; s += v * v; }
    __shared__ float red[256];
    red[tid] = s; __syncthreads();
    for (int st = 128; st > 0; st >>= 1) {
        if (tid < st) red[tid] += red[tid + st];
        __syncthreads();
    }
    float rs = rsqrtf(red[0] / (float)dim + 1e-6f);
    for (int i = tid; i < dim; i += 256) {
        float v = x[xb + i] * rs * g[i];
        bf16 h, l; splitw(v, h, l);
        yh[yb + i] = h; yl[yb + i] = l;
    }
}

// ---------------- pack with RoPE -> bf16 splits (q pre-scaled) ----------------
// qCR [bs][3072] = [qC(2048) | qR(1024)];  kvC [bs][4096] = [kC(2048) | vC]
__global__ __launch_bounds__(256)
void pack_split(const float* __restrict__ qCR, const float* __restrict__ kvC,
                const float* __restrict__ krn, const float* __restrict__ freqs,
                bf16* __restrict__ qfh, bf16* __restrict__ qfl,
                bf16* __restrict__ kfh, bf16* __restrict__ kfl, float scale)
{
    int bs = blockIdx.x;
    int s  = bs & (SEQ - 1);
    LL qfb = (LL)bs * N_HEADS * D_QK;
    int tid = threadIdx.x;

    __shared__ float krs[D_R];
    if (tid < 32) {
        int i = tid;
        float a = krn[(LL)bs*D_R + 2*i];
        float b = krn[(LL)bs*D_R + 2*i + 1];
        float c  = freqs[(LL)s*D_R + 2*i];
        float sn = freqs[(LL)s*D_R + 2*i + 1];
        krs[2*i]   = a*c - b*sn;
        krs[2*i+1] = a*sn + b*c;
    }
    __syncthreads();

    for (int idx = tid; idx < N_HEADS*D_H; idx += 256) {
        int h = idx >> 7, d = idx & 127;
        float v = qCR[(LL)bs*3072 + idx] * scale;
        bf16 hh, ll; splitw(v, hh, ll);
        qfh[qfb + h*D_QK + d] = hh; qfl[qfb + h*D_QK + d] = ll;
    }
    for (int idx = tid; idx < N_HEADS*(D_R/2); idx += 256) {
        int h = idx >> 5, i = idx & 31;
        float a = qCR[(LL)bs*3072 + 2048 + h*D_R + 2*i];
        float b = qCR[(LL)bs*3072 + 2048 + h*D_R + 2*i + 1];
        float c  = freqs[(LL)s*D_R + 2*i];
        float sn = freqs[(LL)s*D_R + 2*i + 1];
        float v0 = (a*c - b*sn) * scale, v1 = (a*sn + b*c) * scale;
        bf16 hh, ll;
        splitw(v0, hh, ll);
        qfh[qfb + h*D_QK + D_H + 2*i] = hh;   qfl[qfb + h*D_QK + D_H + 2*i] = ll;
        splitw(v1, hh, ll);
        qfh[qfb + h*D_QK + D_H + 2*i+1] = hh; qfl[qfb + h*D_QK + D_H + 2*i+1] = ll;
    }
    for (int idx = tid; idx < N_HEADS*D_R; idx += 256) {
        int h = idx >> 6, d = idx & 63;
        bf16 hh, ll; splitw(krs[d], hh, ll);
        kfh[qfb + h*D_QK + d] = hh; kfl[qfb + h*D_QK + d] = ll;
    }
    for (int idx = tid; idx < N_HEADS*D_H; idx += 256) {
        int h = idx >> 7, d = idx & 127;
        float v = kvC[(LL)bs*4096 + idx];
        bf16 hh, ll; splitw(v, hh, ll);
        kfh[qfb + h*D_QK + D_R + d] = hh; kfl[qfb + h*D_QK + D_R + d] = ll;
    }
}

// ---------------- causal softmax + bf16 split emission ----------------
__global__ __launch_bounds__(256)
void softmax_kernel(float* __restrict__ w, bf16* __restrict__ wh, bf16* __restrict__ wl)
{
    LL row = blockIdx.x;
    int q = (int)(row & (SEQ - 1));
    float* base = w + row * (LL)SEQ;
    bf16* bh = wh + row * (LL)SEQ;
    bf16* bl = wl + row * (LL)SEQ;
    int tid = threadIdx.x;

    float vals[8];
    float mx = -INFINITY;
    #pragma unroll
    for (int it = 0; it < 8; it++) {
        int k = tid + it * 256;
        float v = -INFINITY;
        if (k <= q) v = base[k];
        vals[it] = v;
        mx = fmaxf(mx, v);
    }
    __shared__ float red[256];
    red[tid] = mx; __syncthreads();
    for (int st = 128; st > 0; st >>= 1) {
        if (tid < st) red[tid] = fmaxf(red[tid], red[tid + st]);
        __syncthreads();
    }
    mx = red[0]; __syncthreads();

    float sum = 0.0f;
    #pragma unroll
    for (int it = 0; it < 8; it++) {
        float e = (vals[it] == -INFINITY) ? 0.0f : __expf(vals[it] - mx);
        vals[it] = e;
        sum += e;
    }
    red[tid] = sum; __syncthreads();
    for (int st = 128; st > 0; st >>= 1) {
        if (tid < st) red[tid] += red[tid + st];
        __syncthreads();
    }
    float inv = 1.0f / red[0];

    int kLim = ((q >> 8) + 1) << 8;   // covers PV's Keff = m0+256
    #pragma unroll
    for (int it = 0; it < 8; it++) {
        int k = tid + it * 256;
        float p = vals[it] * inv;
        base[k] = p;
        if (k < kLim) {
            bf16 h, l; splitw(p, h, l);
            bh[k] = h; bl[k] = l;
        }
    }
}

// ---------------- scalar SGEMM for the tiny N=64 kr projection ----------------
__global__ __launch_bounds__(256)
void gemm_small(const float* __restrict__ A, const float* __restrict__ Bm,
                const float* __restrict__ bias, float* __restrict__ C,
                int K, int lda, int ldb, int ldc)
{
    int m0 = blockIdx.y * 64;
    int n0 = blockIdx.x * 64;
    __shared__ float sA[16][68];
    __shared__ float sB[16][68];
    int tid = threadIdx.x;
    int ty = tid >> 4, tx = tid & 15;
    float acc[4][4] = {};
    int arow = tid >> 2, ak = (tid & 3) * 4;
    int brow = tid >> 4, bcol = (tid & 15) * 4;

    for (int k0 = 0; k0 < K; k0 += 16) {
        float4 a4 = *(const float4*)(A + (LL)(m0 + arow) * lda + k0 + ak);
        sA[ak+0][arow] = a4.x; sA[ak+1][arow] = a4.y;
        sA[ak+2][arow] = a4.z; sA[ak+3][arow] = a4.w;
        float4 b4 = *(const float4*)(Bm + (LL)(k0 + brow) * ldb + n0 + bcol);
        *(float4*)&sB[brow][bcol] = b4;
        __syncthreads();
        #pragma unroll
        for (int kk = 0; kk < 16; kk++) {
            float af[4], bf[4];
            *(float4*)af = *(const float4*)&sA[kk][ty*4];
            *(float4*)bf = *(const float4*)&sB[kk][tx*4];
            #pragma unroll
            for (int i = 0; i < 4; i++)
                #pragma unroll
                for (int j = 0; j < 4; j++)
                    acc[i][j] = fmaf(af[i], bf[j], acc[i][j]);
        }
        __syncthreads();
    }
    #pragma unroll
    for (int i = 0; i < 4; i++)
        #pragma unroll
        for (int j = 0; j < 4; j++)
            C[(LL)(m0 + ty*4 + i) * ldc + n0 + tx*4 + j] = acc[i][j] + bias[n0 + tx*4 + j];
}

// ---------------- host ----------------
#define SYMF(name) ({ void* p_; cudaGetSymbolAddress(&p_, name); (float*)p_; })
#define SYMB(name) ({ void* p_; cudaGetSymbolAddress(&p_, name); (bf16*)p_; })

#define G512_SMEM  196608
#define SCORE_SMEM 98304

extern "C" void kernel_launch(void* const* d_in, const int* in_sizes, int n_in,
                              void* d_out, int out_size)
{
    (void)in_sizes; (void)n_in; (void)out_size;
    const float* h       = (const float*)d_in[0];
    const float* freqs   = (const float*)d_in[1];
    const float* Wq_down = (const float*)d_in[3];
    const float* bq_down = (const float*)d_in[4];
    const float* gq_norm = (const float*)d_in[5];
    const float* Wqc     = (const float*)d_in[6];
    const float* bqc     = (const float*)d_in[7];
    const float* Wqr     = (const float*)d_in[8];
    const float* bqr     = (const float*)d_in[9];
    const float* Wkr     = (const float*)d_in[10];
    const float* bkr     = (const float*)d_in[11];
    const float* gkr     = (const float*)d_in[12];
    const float* Wkv     = (const float*)d_in[13];
    const float* bkv     = (const float*)d_in[14];
    const float* gkv     = (const float*)d_in[15];
    const float* Wkc     = (const float*)d_in[16];
    const float* bkc     = (const float*)d_in[17];
    const float* Wvc     = (const float*)d_in[18];
    const float* bvc     = (const float*)d_in[19];
    const float* Wo      = (const float*)d_in[20];
    const float* bo      = (const float*)d_in[21];

    float* out_h = (float*)d_out;
    float* w     = out_h + (LL)NTOK * D_MODEL;

    float* tmp12 = SYMF(g_tmp12);
    float* qCR = SYMF(g_qCR);
    float* kvC = SYMF(g_kvC);
    float* kr = SYMF(g_kr);   float* krn = SYMF(g_krn);
    float* b1 = SYMF(g_bias1); float* b2 = SYMF(g_bias2); float* b3 = SYMF(g_bias3);

    bf16 *h_hi = SYMB(g_h_hi), *h_lo = SYMB(g_h_lo);
    bf16 *WdT_hi = SYMB(g_WdT_hi), *WdT_lo = SYMB(g_WdT_lo);
    bf16 *WqcrT_hi = SYMB(g_WqcrT_hi), *WqcrT_lo = SYMB(g_WqcrT_lo);
    bf16 *WkvcT_hi = SYMB(g_WkvcT_hi), *WkvcT_lo = SYMB(g_WkvcT_lo);
    bf16 *WoT_hi  = SYMB(g_WoT_hi),  *WoT_lo  = SYMB(g_WoT_lo);
    bf16 *cQ_hi = SYMB(g_cQ_hi), *cQ_lo = SYMB(g_cQ_lo);
    bf16 *cKV_hi = SYMB(g_cKV_hi), *cKV_lo = SYMB(g_cKV_lo);
    bf16 *qf_hi = SYMB(g_qf_hi), *qf_lo = SYMB(g_qf_lo);
    bf16 *kf_hi = SYMB(g_kf_hi), *kf_lo = SYMB(g_kf_lo);
    bf16 *vCT_hi = SYMB(g_vCT_hi), *vCT_lo = SYMB(g_vCT_lo);
    bf16 *w_hi = SYMB(g_w_hi), *w_lo = SYMB(g_w_lo);
    bf16 *attn_hi = SYMB(g_attn_hi), *attn_lo = SYMB(g_attn_lo);

    cudaFuncSetAttribute((const void*)gemm512<0,false>, cudaFuncAttributeMaxDynamicSharedMemorySize, G512_SMEM);
    cudaFuncSetAttribute((const void*)gemm512<2,true>,  cudaFuncAttributeMaxDynamicSharedMemorySize, G512_SMEM);
    cudaFuncSetAttribute(score_gemm, cudaFuncAttributeMaxDynamicSharedMemorySize, SCORE_SMEM);

    // prep: biases + input/weight splits for the first merged GEMM
    biascat<<<16, 256>>>(bq_down, bkv, bqc, bqr, bkc, bvc, b1, b2, b3);
    split_rm<<<(LL)NTOK*D_MODEL/1024, 256>>>(h, h_hi, h_lo);
    split_tr<<<dim3(D_CQ/32, D_MODEL/32), 256>>>(Wq_down, D_CQ, WdT_hi, WdT_lo, D_MODEL, D_CQ);
    split_tr<<<dim3(D_C/32, D_MODEL/32), 256>>>(Wkv, D_C,
        WdT_hi + (LL)D_CQ*D_MODEL, WdT_lo + (LL)D_CQ*D_MODEL, D_MODEL, D_C);

    // merged: tmp12 = h @ [Wq_down | Wkv] + [bq_down | bkv]   (N=2048)
    gemm512<0,false><<<dim3(2048/128, NTOK/256), 512, G512_SMEM>>>(
        h_hi, h_lo, WdT_hi, WdT_lo, b1, tmp12, nullptr, nullptr,
        D_MODEL, D_MODEL, D_MODEL, 2048, 0,0,0,0,0,0,1);

    // remaining weight splits (merged buffers)
    split_tr<<<dim3(2048/32, D_CQ/32), 256>>>(Wqc, 2048, WqcrT_hi, WqcrT_lo, D_CQ, 2048);
    split_tr<<<dim3(1024/32, D_CQ/32), 256>>>(Wqr, 1024,
        WqcrT_hi + (LL)2048*D_CQ, WqcrT_lo + (LL)2048*D_CQ, D_CQ, 1024);
    split_tr<<<dim3(2048/32, D_C/32), 256>>>(Wkc, 2048, WkvcT_hi, WkvcT_lo, D_C, 2048);
    split_tr<<<dim3(2048/32, D_C/32), 256>>>(Wvc, 2048,
        WkvcT_hi + (LL)2048*D_C, WkvcT_lo + (LL)2048*D_C, D_C, 2048);
    split_tr<<<dim3(2048/32, 2048/32), 256>>>(Wo, 2048, WoT_hi, WoT_lo, 2048, 2048);

    // norms -> bf16 splits
    rmsnorm_split<<<NTOK, 256>>>(tmp12, 2048, 0,    gq_norm, cQ_hi, cQ_lo, D_CQ);
    rmsnorm_split<<<NTOK, 256>>>(tmp12, 2048, D_CQ, gkv,     cKV_hi, cKV_lo, D_C);

    // merged: qCR = cQ @ [Wqc | Wqr] + [bqc | bqr]   (N=3072)
    gemm512<0,false><<<dim3(3072/128, NTOK/256), 512, G512_SMEM>>>(
        cQ_hi, cQ_lo, WqcrT_hi, WqcrT_lo, b2, qCR, nullptr, nullptr,
        D_CQ, D_CQ, D_CQ, 3072, 0,0,0,0,0,0,1);

    // kr (scalar) + rmsnorm
    gemm_small<<<dim3(1, NTOK/64), 256>>>(h, Wkr, bkr, kr, D_MODEL, D_MODEL, D_R, D_R);
    rmsnorm_kernel<<<NTOK, 256>>>(kr, gkr, krn, D_R);

    // merged: kvC = cKV @ [Wkc | Wvc] + [bkc | bvc]   (N=4096)
    gemm512<0,false><<<dim3(4096/128, NTOK/256), 512, G512_SMEM>>>(
        cKV_hi, cKV_lo, WkvcT_hi, WkvcT_lo, b3, kvC, nullptr, nullptr,
        D_C, D_C, D_C, 4096, 0,0,0,0,0,0,1);

    // vC^T splits (vC = cols 2048..4095 of kvC)
    split_tr<<<dim3(2048/32, NTOK/32), 256>>>(kvC + 2048, 4096, vCT_hi, vCT_lo, NTOK, 2048);

    // pack + RoPE (q pre-scaled)
    pack_split<<<NTOK, 256>>>(qCR, kvC, krn, freqs, qf_hi, qf_lo, kf_hi, kf_lo,
                              1.0f / sqrtf((float)D_QK));

    // scores = q k^T (causal tiles, 2 CTAs/SM)
    score_gemm<<<dim3(SEQ/128, SEQ/128, BSZ*N_HEADS), 256, SCORE_SMEM>>>(
        qf_hi, qf_lo, kf_hi, kf_lo, w);

    // softmax
    softmax_kernel<<<(LL)BSZ*N_HEADS*SEQ, 256>>>(w, w_hi, w_lo);

    // PV: attn = w @ vC (K clipped at diagonal), bf16-split output
    {
        LL soW = (LL)N_HEADS * SEQ * SEQ, siW = (LL)SEQ * SEQ;
        LL soB = 2048;
        LL siB = (LL)D_H * NTOK;
        LL soC = (LL)SEQ * 2048, siC = D_H;
        gemm512<2,true><<<dim3(D_H/128, SEQ/256, BSZ*N_HEADS), 512, G512_SMEM>>>(
            w_hi, w_lo, vCT_hi, vCT_lo, nullptr, nullptr, attn_hi, attn_lo,
            SEQ, SEQ, NTOK, 2048,
            soW, siW, soB, siB, soC, siC, N_HEADS);
    }

    // h_out = attn @ Wo + bo
    gemm512<0,false><<<dim3(2048/128, NTOK/256), 512, G512_SMEM>>>(
        attn_hi, attn_lo, WoT_hi, WoT_lo, bo, out_h, nullptr, nullptr,
        2048, 2048, 2048, 2048, 0,0,0,0,0,0,1);
}

// round 11
// speedup vs baseline: 2.2168x; 1.0156x over previous
#include <cuda_runtime.h>
#include <cuda_bf16.h>
#include <math.h>
#include <stdint.h>

#define D_MODEL 2048
#define N_HEADS 16
#define D_CQ    1536
#define D_C     512
#define D_H     128
#define D_R     64
#define BSZ     4
#define SEQ     2048
#define NTOK    (BSZ*SEQ)
#define D_QK    (D_H + D_R)
#define LL long long

#define SW128(o) ((o) ^ (((o) >> 3) & 0x70))
#define SW64(o)  ((o) ^ (((o) >> 2) & 0x30))

#define N1 2176   // merged first-GEMM N: Wqd(1536) | Wkv(512) | Wkr(64) | pad(64)

typedef __nv_bfloat16 bf16;

// ---------------- scratch ----------------
__device__ float g_tmp12[(LL)NTOK * N1];           // [cQpre | cKVpre | krpre | pad]
__device__ float g_qCR [(LL)NTOK * 3072];          // [qC | qR]
__device__ float g_kvC [(LL)NTOK * 4096];          // [kC | vC]
__device__ float g_krn [(LL)NTOK * D_R];
__device__ bf16 g_h_hi[(LL)NTOK * D_MODEL],      g_h_lo[(LL)NTOK * D_MODEL];
__device__ bf16 g_WdT_hi[(LL)N1 * D_MODEL],      g_WdT_lo[(LL)N1 * D_MODEL];
__device__ bf16 g_WqcrT_hi[(LL)3072 * D_CQ],     g_WqcrT_lo[(LL)3072 * D_CQ];
__device__ bf16 g_WkvcT_hi[(LL)4096 * D_C],      g_WkvcT_lo[(LL)4096 * D_C];
__device__ bf16 g_WoT_hi[(LL)2048 * 2048],       g_WoT_lo[(LL)2048 * 2048];
__device__ bf16 g_cQ_hi[(LL)NTOK * D_CQ],        g_cQ_lo[(LL)NTOK * D_CQ];
__device__ bf16 g_cKV_hi[(LL)NTOK * D_C],        g_cKV_lo[(LL)NTOK * D_C];
__device__ bf16 g_qf_hi[(LL)NTOK * N_HEADS*D_QK], g_qf_lo[(LL)NTOK * N_HEADS*D_QK];
__device__ bf16 g_kf_hi[(LL)NTOK * N_HEADS*D_QK], g_kf_lo[(LL)NTOK * N_HEADS*D_QK];
__device__ bf16 g_vCT_hi[(LL)2048 * NTOK],       g_vCT_lo[(LL)2048 * NTOK];
__device__ bf16 g_w_hi[(LL)BSZ*N_HEADS*SEQ*SEQ], g_w_lo[(LL)BSZ*N_HEADS*SEQ*SEQ];
__device__ bf16 g_attn_hi[(LL)NTOK * 2048],      g_attn_lo[(LL)NTOK * 2048];
__device__ float g_bias1[N1];     // [bq_down | bkv | bkr | 0]
__device__ float g_bias2[3072];   // [bqc | bqr]
__device__ float g_bias3[4096];   // [bkc | bvc]

// ---------------- helpers ----------------
__device__ __forceinline__ uint32_t smem_u32(const void* p) {
    uint32_t a;
    asm("{ .reg .u64 t; cvta.to.shared.u64 t, %1; cvt.u32.u64 %0, t; }" : "=r"(a) : "l"(p));
    return a;
}
#define CP16(d, s) asm volatile("cp.async.cg.shared.global [%0], [%1], 16;" :: "r"(d), "l"(s))
#define CP_COMMIT() asm volatile("cp.async.commit_group;" ::: "memory")
#define CP_WAIT1() asm volatile("cp.async.wait_group 1;" ::: "memory")
#define CP_WAIT0() asm volatile("cp.async.wait_group 0;" ::: "memory")

__device__ __forceinline__ void ldsm_x4(uint32_t addr, uint32_t& r0, uint32_t& r1,
                                        uint32_t& r2, uint32_t& r3) {
    asm volatile("ldmatrix.sync.aligned.m8n8.x4.shared.b16 {%0,%1,%2,%3}, [%4];"
                 : "=r"(r0), "=r"(r1), "=r"(r2), "=r"(r3) : "r"(addr));
}
__device__ __forceinline__ void mma_bf16(float* c, const uint32_t* a,
                                         uint32_t b0, uint32_t b1) {
    asm volatile(
        "mma.sync.aligned.m16n8k16.row.col.f32.bf16.bf16.f32 "
        "{%0,%1,%2,%3}, {%4,%5,%6,%7}, {%8,%9}, {%0,%1,%2,%3};"
        : "+f"(c[0]), "+f"(c[1]), "+f"(c[2]), "+f"(c[3])
        : "r"(a[0]), "r"(a[1]), "r"(a[2]), "r"(a[3]), "r"(b0), "r"(b1));
}
__device__ __forceinline__ void splitw(float v, bf16& hi, bf16& lo) {
    hi = __float2bfloat16(v);
    lo = __float2bfloat16(v - __bfloat162float(hi));
}

// ============ bf16x3 GEMM: 256x128 tile, 512 threads, BK=64, 2-stage ============
// EPI: 0=fp32+bias, 2=bf16 splits.  KCLIP: Keff = min(m0+256, K).
template<int EPI, bool KCLIP>
__global__ __launch_bounds__(512, 1)
void gemm512(const bf16* __restrict__ Ahi, const bf16* __restrict__ Alo,
             const bf16* __restrict__ Bhi, const bf16* __restrict__ Blo,
             const float* __restrict__ bias,
             float* __restrict__ C, bf16* __restrict__ Chi, bf16* __restrict__ Clo,
             int K, int lda, int ldb, int ldc,
             LL soA, LL siA, LL soB, LL siB, LL soC, LL siC, int IC)
{
    int m0 = blockIdx.y * 256;
    int n0 = blockIdx.x * 128;

    int z = blockIdx.z;
    LL zo = z / IC, zi = z % IC;
    const bf16* Ah_b = Ahi + zo*soA + zi*siA;
    const bf16* Al_b = Alo + zo*soA + zi*siA;
    const bf16* Bh_b = Bhi + zo*soB + zi*siB;
    const bf16* Bl_b = Blo + zo*soB + zi*siB;

    int Keff = KCLIP ? (m0 + 256 < K ? m0 + 256 : K) : K;
    int KT = Keff >> 6;

    extern __shared__ char sm[];
    uint32_t sb = smem_u32(sm);

    int tid = threadIdx.x;
    int wid = tid >> 5, lane = tid & 31;
    int wm = (wid & 7) << 5;
    int wn = (wid >> 3) << 6;
    int g = lane >> 3, r = lane & 7;
    int aro = ((g & 1) << 3) + r, aco = (g >> 1) << 4;
    int bro = ((g >> 1) << 3) + r, bco = (g & 1) << 4;

    float acc[2][8][4];
    #pragma unroll
    for (int i = 0; i < 2; i++)
        #pragma unroll
        for (int j = 0; j < 8; j++)
            #pragma unroll
            for (int t = 0; t < 4; t++) acc[i][j][t] = 0.0f;

    #define LOAD_STG(s, k0) do {                                               \
        uint32_t st = sb + (uint32_t)(s) * 98304u;                             \
        _Pragma("unroll")                                                      \
        for (int i = 0; i < 4; i++) {                                          \
            int idx = tid + (i << 9);                                          \
            int row = idx >> 3, c = idx & 7;                                   \
            uint32_t d = st + SW128((uint32_t)((row << 7) + (c << 4)));        \
            LL go = (LL)(m0 + row) * lda + (k0) + (c << 3);                    \
            CP16(d,          Ah_b + go);                                       \
            CP16(d + 32768u, Al_b + go);                                       \
        }                                                                      \
        _Pragma("unroll")                                                      \
        for (int i = 0; i < 2; i++) {                                          \
            int idx = tid + (i << 9);                                          \
            int row = idx >> 3, c = idx & 7;                                   \
            uint32_t d = st + 65536u + SW128((uint32_t)((row << 7) + (c << 4)));\
            LL go = (LL)(n0 + row) * ldb + (k0) + (c << 3);                    \
            CP16(d,          Bh_b + go);                                       \
            CP16(d + 16384u, Bl_b + go);                                       \
        }                                                                      \
    } while (0)

    LOAD_STG(0, 0);
    CP_COMMIT();

    for (int kt = 0; kt < KT; kt++) {
        CP_WAIT0();
        __syncthreads();
        if (kt + 1 < KT) {
            LOAD_STG((kt + 1) & 1, (kt + 1) << 6);
            CP_COMMIT();
        }

        uint32_t aB = sb + (uint32_t)(kt & 1) * 98304u;
        uint32_t bB = aB + 65536u;

        #pragma unroll
        for (int ks = 0; ks < 4; ks++) {
            int kb = ks << 5;
            uint32_t ah[2][4], al[2][4];
            #pragma unroll
            for (int mf = 0; mf < 2; mf++) {
                uint32_t off = SW128((uint32_t)((wm + (mf << 4) + aro) * 128 + kb + aco));
                ldsm_x4(aB + off,          ah[mf][0], ah[mf][1], ah[mf][2], ah[mf][3]);
                ldsm_x4(aB + 32768u + off, al[mf][0], al[mf][1], al[mf][2], al[mf][3]);
            }
            #pragma unroll
            for (int ng = 0; ng < 4; ng++) {
                uint32_t off = SW128((uint32_t)((wn + (ng << 4) + bro) * 128 + kb + bco));
                uint32_t bh0, bh1, bh2, bh3, bl0, bl1, bl2, bl3;
                ldsm_x4(bB + off,          bh0, bh1, bh2, bh3);
                ldsm_x4(bB + 16384u + off, bl0, bl1, bl2, bl3);
                #pragma unroll
                for (int mf = 0; mf < 2; mf++) {
                    float* c0 = acc[mf][(ng << 1)];
                    float* c1 = acc[mf][(ng << 1) + 1];
                    mma_bf16(c0, ah[mf], bh0, bh1);
                    mma_bf16(c1, ah[mf], bh2, bh3);
                    mma_bf16(c0, ah[mf], bl0, bl1);
                    mma_bf16(c1, ah[mf], bl2, bl3);
                    mma_bf16(c0, al[mf], bh0, bh1);
                    mma_bf16(c1, al[mf], bh2, bh3);
                }
            }
        }
    }

    #pragma unroll
    for (int mf = 0; mf < 2; mf++) {
        int row = m0 + wm + (mf << 4) + (lane >> 2);
        #pragma unroll
        for (int nf = 0; nf < 8; nf++) {
            int col = n0 + wn + (nf << 3) + ((lane & 3) << 1);
            float* a = acc[mf][nf];
            if (EPI == 0) {
                float bx = bias[col], by = bias[col + 1];
                float* Cb = C + zo*soC + zi*siC;
                *(float2*)(Cb + (LL)row * ldc + col)       = make_float2(a[0] + bx, a[1] + by);
                *(float2*)(Cb + (LL)(row + 8) * ldc + col) = make_float2(a[2] + bx, a[3] + by);
            } else {
                bf16* Hb = Chi + zo*soC + zi*siC;
                bf16* Lb = Clo + zo*soC + zi*siC;
                bf16 h0, l0, h1, l1;
                splitw(a[0], h0, l0); splitw(a[1], h1, l1);
                uint32_t hp = ((uint32_t)__bfloat16_as_ushort(h1) << 16) | __bfloat16_as_ushort(h0);
                uint32_t lp = ((uint32_t)__bfloat16_as_ushort(l1) << 16) | __bfloat16_as_ushort(l0);
                *(uint32_t*)(Hb + (LL)row * ldc + col) = hp;
                *(uint32_t*)(Lb + (LL)row * ldc + col) = lp;
                splitw(a[2], h0, l0); splitw(a[3], h1, l1);
                hp = ((uint32_t)__bfloat16_as_ushort(h1) << 16) | __bfloat16_as_ushort(h0);
                lp = ((uint32_t)__bfloat16_as_ushort(l1) << 16) | __bfloat16_as_ushort(l0);
                *(uint32_t*)(Hb + (LL)(row + 8) * ldc + col) = hp;
                *(uint32_t*)(Lb + (LL)(row + 8) * ldc + col) = lp;
            }
        }
    }
}

// ============ score GEMM: bf16x3, 128x128, BK=32, 3-stage, 2 CTAs/SM, causal ============
// Upper (fully masked) tiles write zeros to w instead of returning:
// rides in the compute CTAs' memory shadow, and lets softmax skip those writes.
__global__ __launch_bounds__(256, 2)
void score_gemm(const bf16* __restrict__ Ahi, const bf16* __restrict__ Alo,
                const bf16* __restrict__ Bhi, const bf16* __restrict__ Blo,
                float* __restrict__ W)
{
    int m0 = blockIdx.y * 128;
    int n0 = blockIdx.x * 128;
    int z = blockIdx.z;
    float* Wb = W + (LL)z * SEQ * SEQ;

    int tid = threadIdx.x;

    if (n0 > m0) {
        // fully masked tile: write zeros (p = 0 above diagonal)
        float4 zz = make_float4(0.f, 0.f, 0.f, 0.f);
        #pragma unroll
        for (int i = 0; i < 16; i++) {
            int idx = tid + (i << 8);
            int row = idx >> 5, c4 = (idx & 31) << 2;
            *(float4*)(Wb + (LL)(m0 + row) * SEQ + n0 + c4) = zz;
        }
        return;
    }

    int b = z >> 4, hh = z & 15;
    const LL lda = (LL)N_HEADS * D_QK;
    LL abase = (LL)b * SEQ * lda + (LL)hh * D_QK;
    const bf16* Ah_b = Ahi + abase;
    const bf16* Al_b = Alo + abase;
    const bf16* Bh_b = Bhi + abase;
    const bf16* Bl_b = Blo + abase;

    extern __shared__ char sm[];
    uint32_t sb = smem_u32(sm);

    int wid = tid >> 5, lane = tid & 31;
    int wm = (wid & 3) << 5;
    int wn = (wid >> 2) << 6;
    int g = lane >> 3, r = lane & 7;
    int aro = ((g & 1) << 3) + r, aco = (g >> 1) << 4;
    int bro = ((g >> 1) << 3) + r, bco = (g & 1) << 4;

    float acc[2][8][4];
    #pragma unroll
    for (int i = 0; i < 2; i++)
        #pragma unroll
        for (int j = 0; j < 8; j++)
            #pragma unroll
            for (int t = 0; t < 4; t++) acc[i][j][t] = 0.0f;

    #define SLOAD(s, k0) do {                                                  \
        uint32_t st = sb + (uint32_t)(s) * 32768u;                             \
        _Pragma("unroll")                                                      \
        for (int i = 0; i < 2; i++) {                                          \
            int idx = tid + (i << 8);                                          \
            int row = idx >> 2, c = (idx & 3) << 4;                            \
            uint32_t sw = SW64((uint32_t)((row << 6) + c));                    \
            LL goA = (LL)(m0 + row) * lda + (k0) + ((idx & 3) << 3);           \
            LL goB = (LL)(n0 + row) * lda + (k0) + ((idx & 3) << 3);           \
            CP16(st + sw,           Ah_b + goA);                               \
            CP16(st + 8192u  + sw,  Al_b + goA);                               \
            CP16(st + 16384u + sw,  Bh_b + goB);                               \
            CP16(st + 24576u + sw,  Bl_b + goB);                               \
        }                                                                      \
    } while (0)

    const int KT = D_QK / 32;   // 6
    SLOAD(0, 0);  CP_COMMIT();
    SLOAD(1, 32); CP_COMMIT();

    int cs = 0, ls = 2;
    for (int kt = 0; kt < KT; kt++) {
        CP_WAIT1();
        __syncthreads();
        if (kt + 2 < KT) {
            SLOAD(ls, (kt + 2) << 5);
        }
        CP_COMMIT();
        ls++; if (ls == 3) ls = 0;

        uint32_t aB = sb + (uint32_t)cs * 32768u;
        uint32_t bB = aB + 16384u;

        #pragma unroll
        for (int ks = 0; ks < 2; ks++) {
            int kb = ks << 5;
            uint32_t ah[2][4], al[2][4];
            #pragma unroll
            for (int mf = 0; mf < 2; mf++) {
                uint32_t off = SW64((uint32_t)((wm + (mf << 4) + aro) * 64 + kb + aco));
                ldsm_x4(aB + off,         ah[mf][0], ah[mf][1], ah[mf][2], ah[mf][3]);
                ldsm_x4(aB + 8192u + off, al[mf][0], al[mf][1], al[mf][2], al[mf][3]);
            }
            #pragma unroll
            for (int ng = 0; ng < 4; ng++) {
                uint32_t off = SW64((uint32_t)((wn + (ng << 4) + bro) * 64 + kb + bco));
                uint32_t bh0, bh1, bh2, bh3, bl0, bl1, bl2, bl3;
                ldsm_x4(bB + off,         bh0, bh1, bh2, bh3);
                ldsm_x4(bB + 8192u + off, bl0, bl1, bl2, bl3);
                #pragma unroll
                for (int mf = 0; mf < 2; mf++) {
                    float* c0 = acc[mf][(ng << 1)];
                    float* c1 = acc[mf][(ng << 1) + 1];
                    mma_bf16(c0, ah[mf], bh0, bh1);
                    mma_bf16(c1, ah[mf], bh2, bh3);
                    mma_bf16(c0, ah[mf], bl0, bl1);
                    mma_bf16(c1, ah[mf], bl2, bl3);
                    mma_bf16(c0, al[mf], bh0, bh1);
                    mma_bf16(c1, al[mf], bh2, bh3);
                }
            }
        }
        cs++; if (cs == 3) cs = 0;
    }

    #pragma unroll
    for (int mf = 0; mf < 2; mf++) {
        int row = m0 + wm + (mf << 4) + (lane >> 2);
        #pragma unroll
        for (int nf = 0; nf < 8; nf++) {
            int col = n0 + wn + (nf << 3) + ((lane & 3) << 1);
            float* a = acc[mf][nf];
            *(float2*)(Wb + (LL)row * SEQ + col)       = make_float2(a[0], a[1]);
            *(float2*)(Wb + (LL)(row + 8) * SEQ + col) = make_float2(a[2], a[3]);
        }
    }
}

// ---------------- split kernels ----------------
__global__ __launch_bounds__(256)
void split_rm(const float* __restrict__ x, bf16* __restrict__ hi, bf16* __restrict__ lo)
{
    LL base = ((LL)blockIdx.x * 256 + threadIdx.x) * 4;
    float4 v = *(const float4*)(x + base);
    bf16 h[4], l[4];
    splitw(v.x, h[0], l[0]); splitw(v.y, h[1], l[1]);
    splitw(v.z, h[2], l[2]); splitw(v.w, h[3], l[3]);
    *(uint2*)(hi + base) = *(uint2*)h;
    *(uint2*)(lo + base) = *(uint2*)l;
}

// x[R rows][ldx cols] fp32 (use cols 0..C-1) -> dest[C rows][R cols] bf16 hi/lo
__global__ __launch_bounds__(256)
void split_tr(const float* __restrict__ x, int ldx,
              bf16* __restrict__ hi, bf16* __restrict__ lo, int R, int C)
{
    __shared__ float s[32][33];
    int tx = threadIdx.x & 31, ty = threadIdx.x >> 5;
    int r0 = blockIdx.y * 32, c0 = blockIdx.x * 32;
    #pragma unroll
    for (int j = 0; j < 4; j++)
        s[ty + 8*j][tx] = x[(LL)(r0 + ty + 8*j) * ldx + c0 + tx];
    __syncthreads();
    #pragma unroll
    for (int j = 0; j < 4; j++) {
        float v = s[tx][ty + 8*j];
        bf16 h, l; splitw(v, h, l);
        LL o = (LL)(c0 + ty + 8*j) * R + r0 + tx;
        hi[o] = h; lo[o] = l;
    }
}

// zero-fill a bf16 region (for weight pad rows)
__global__ __launch_bounds__(256)
void zfill(bf16* __restrict__ p, LL n)
{
    LL i = ((LL)blockIdx.x * 256 + threadIdx.x) * 2;
    if (i < n) *(uint32_t*)(p + i) = 0u;
}

// ---------------- bias concat (padded) ----------------
__global__ __launch_bounds__(256)
void biascat(const float* __restrict__ bqd, const float* __restrict__ bkv,
             const float* __restrict__ bkr,
             const float* __restrict__ bqc, const float* __restrict__ bqr,
             const float* __restrict__ bkc, const float* __restrict__ bvc,
             float* __restrict__ b1, float* __restrict__ b2, float* __restrict__ b3)
{
    int i = blockIdx.x * 256 + threadIdx.x;
    if (i < N1) {
        float v = 0.0f;
        if (i < 1536) v = bqd[i];
        else if (i < 2048) v = bkv[i - 1536];
        else if (i < 2112) v = bkr[i - 2048];
        b1[i] = v;
    }
    if (i < 2048) b2[i] = bqc[i]; else if (i < 3072) b2[i] = bqr[i - 2048];
    if (i < 2048) b3[i] = bkc[i]; else if (i < 4096) b3[i] = bvc[i - 2048];
}

// rmsnorm over a column-slice, fp32 out
__global__ __launch_bounds__(256)
void rmsnorm_slice(const float* __restrict__ x, int ldx, int off,
                   const float* __restrict__ g, float* __restrict__ y, int dim)
{
    LL xb = (LL)blockIdx.x * ldx + off;
    LL yb = (LL)blockIdx.x * dim;
    int tid = threadIdx.x;
    float s = 0.0f;
    for (int i = tid; i < dim; i += 256) { float v = x[xb + i]; s += v * v; }
    __shared__ float red[256];
    red[tid] = s; __syncthreads();
    for (int st = 128; st > 0; st >>= 1) {
        if (tid < st) red[tid] += red[tid + st];
        __syncthreads();
    }
    float rs = rsqrtf(red[0] / (float)dim + 1e-6f);
    for (int i = tid; i < dim; i += 256)
        y[yb + i] = x[xb + i] * rs * g[i];
}

// rmsnorm over a column-slice -> bf16 splits
__global__ __launch_bounds__(256)
void rmsnorm_split(const float* __restrict__ x, int ldx, int off,
                   const float* __restrict__ g,
                   bf16* __restrict__ yh, bf16* __restrict__ yl, int dim)
{
    LL xb = (LL)blockIdx.x * ldx + off;
    LL yb = (LL)blockIdx.x * dim;
    int tid = threadIdx.x;
    float s = 0.0f;
    for (int i = tid; i < dim; i += 256) { float v = x[xb + i]; s += v * v; }
    __shared__ float red[256];
    red[tid] = s; __syncthreads();
    for (int st = 128; st > 0; st >>= 1) {
        if (tid < st) red[tid] += red[tid + st];
        __syncthreads();
    }
    float rs = rsqrtf(red[0] / (float)dim + 1e-6f);
    for (int i = tid; i < dim; i += 256) {
        float v = x[xb + i] * rs * g[i];
        bf16 h, l; splitw(v, h, l);
        yh[yb + i] = h; yl[yb + i] = l;
    }
}

// ---------------- pack with RoPE -> bf16 splits (q pre-scaled) ----------------
__global__ __launch_bounds__(256)
void pack_split(const float* __restrict__ qCR, const float* __restrict__ kvC,
                const float* __restrict__ krn, const float* __restrict__ freqs,
                bf16* __restrict__ qfh, bf16* __restrict__ qfl,
                bf16* __restrict__ kfh, bf16* __restrict__ kfl, float scale)
{
    int bs = blockIdx.x;
    int s  = bs & (SEQ - 1);
    LL qfb = (LL)bs * N_HEADS * D_QK;
    int tid = threadIdx.x;

    __shared__ float krs[D_R];
    if (tid < 32) {
        int i = tid;
        float a = krn[(LL)bs*D_R + 2*i];
        float b = krn[(LL)bs*D_R + 2*i + 1];
        float c  = freqs[(LL)s*D_R + 2*i];
        float sn = freqs[(LL)s*D_R + 2*i + 1];
        krs[2*i]   = a*c - b*sn;
        krs[2*i+1] = a*sn + b*c;
    }
    __syncthreads();

    for (int idx = tid; idx < N_HEADS*D_H; idx += 256) {
        int h = idx >> 7, d = idx & 127;
        float v = qCR[(LL)bs*3072 + idx] * scale;
        bf16 hh, ll; splitw(v, hh, ll);
        qfh[qfb + h*D_QK + d] = hh; qfl[qfb + h*D_QK + d] = ll;
    }
    for (int idx = tid; idx < N_HEADS*(D_R/2); idx += 256) {
        int h = idx >> 5, i = idx & 31;
        float a = qCR[(LL)bs*3072 + 2048 + h*D_R + 2*i];
        float b = qCR[(LL)bs*3072 + 2048 + h*D_R + 2*i + 1];
        float c  = freqs[(LL)s*D_R + 2*i];
        float sn = freqs[(LL)s*D_R + 2*i + 1];
        float v0 = (a*c - b*sn) * scale, v1 = (a*sn + b*c) * scale;
        bf16 hh, ll;
        splitw(v0, hh, ll);
        qfh[qfb + h*D_QK + D_H + 2*i] = hh;   qfl[qfb + h*D_QK + D_H + 2*i] = ll;
        splitw(v1, hh, ll);
        qfh[qfb + h*D_QK + D_H + 2*i+1] = hh; qfl[qfb + h*D_QK + D_H + 2*i+1] = ll;
    }
    for (int idx = tid; idx < N_HEADS*D_R; idx += 256) {
        int h = idx >> 6, d = idx & 63;
        bf16 hh, ll; splitw(krs[d], hh, ll);
        kfh[qfb + h*D_QK + d] = hh; kfl[qfb + h*D_QK + d] = ll;
    }
    for (int idx = tid; idx < N_HEADS*D_H; idx += 256) {
        int h = idx >> 7, d = idx & 127;
        float v = kvC[(LL)bs*4096 + idx];
        bf16 hh, ll; splitw(v, hh, ll);
        kfh[qfb + h*D_QK + D_R + d] = hh; kfl[qfb + h*D_QK + D_R + d] = ll;
    }
}

// ---------------- causal softmax (writes only k < kLim; zeros beyond pre-written) ----------------
__global__ __launch_bounds__(256)
void softmax_kernel(float* __restrict__ w, bf16* __restrict__ wh, bf16* __restrict__ wl)
{
    LL row = blockIdx.x;
    int q = (int)(row & (SEQ - 1));
    float* base = w + row * (LL)SEQ;
    bf16* bh = wh + row * (LL)SEQ;
    bf16* bl = wl + row * (LL)SEQ;
    int tid = threadIdx.x;

    float vals[8];
    float mx = -INFINITY;
    #pragma unroll
    for (int it = 0; it < 8; it++) {
        int k = tid + it * 256;
        float v = -INFINITY;
        if (k <= q) v = base[k];
        vals[it] = v;
        mx = fmaxf(mx, v);
    }
    __shared__ float red[256];
    red[tid] = mx; __syncthreads();
    for (int st = 128; st > 0; st >>= 1) {
        if (tid < st) red[tid] = fmaxf(red[tid], red[tid + st]);
        __syncthreads();
    }
    mx = red[0]; __syncthreads();

    float sum = 0.0f;
    #pragma unroll
    for (int it = 0; it < 8; it++) {
        float e = (vals[it] == -INFINITY) ? 0.0f : __expf(vals[it] - mx);
        vals[it] = e;
        sum += e;
    }
    red[tid] = sum; __syncthreads();
    for (int st = 128; st > 0; st >>= 1) {
        if (tid < st) red[tid] += red[tid + st];
        __syncthreads();
    }
    float inv = 1.0f / red[0];

    int kLim = ((q >> 8) + 1) << 8;   // covers PV's Keff = m0+256; beyond is pre-zeroed
    #pragma unroll
    for (int it = 0; it < 8; it++) {
        int k = tid + it * 256;
        if (k < kLim) {
            float p = vals[it] * inv;
            base[k] = p;
            bf16 h, l; splitw(p, h, l);
            bh[k] = h; bl[k] = l;
        }
    }
}

// ---------------- host ----------------
#define SYMF(name) ({ void* p_; cudaGetSymbolAddress(&p_, name); (float*)p_; })
#define SYMB(name) ({ void* p_; cudaGetSymbolAddress(&p_, name); (bf16*)p_; })

#define G512_SMEM  196608
#define SCORE_SMEM 98304

extern "C" void kernel_launch(void* const* d_in, const int* in_sizes, int n_in,
                              void* d_out, int out_size)
{
    (void)in_sizes; (void)n_in; (void)out_size;
    const float* h       = (const float*)d_in[0];
    const float* freqs   = (const float*)d_in[1];
    const float* Wq_down = (const float*)d_in[3];
    const float* bq_down = (const float*)d_in[4];
    const float* gq_norm = (const float*)d_in[5];
    const float* Wqc     = (const float*)d_in[6];
    const float* bqc     = (const float*)d_in[7];
    const float* Wqr     = (const float*)d_in[8];
    const float* bqr     = (const float*)d_in[9];
    const float* Wkr     = (const float*)d_in[10];
    const float* bkr     = (const float*)d_in[11];
    const float* gkr     = (const float*)d_in[12];
    const float* Wkv     = (const float*)d_in[13];
    const float* bkv     = (const float*)d_in[14];
    const float* gkv     = (const float*)d_in[15];
    const float* Wkc     = (const float*)d_in[16];
    const float* bkc     = (const float*)d_in[17];
    const float* Wvc     = (const float*)d_in[18];
    const float* bvc     = (const float*)d_in[19];
    const float* Wo      = (const float*)d_in[20];
    const float* bo      = (const float*)d_in[21];

    float* out_h = (float*)d_out;
    float* w     = out_h + (LL)NTOK * D_MODEL;

    float* tmp12 = SYMF(g_tmp12);
    float* qCR = SYMF(g_qCR);
    float* kvC = SYMF(g_kvC);
    float* krn = SYMF(g_krn);
    float* b1 = SYMF(g_bias1); float* b2 = SYMF(g_bias2); float* b3 = SYMF(g_bias3);

    bf16 *h_hi = SYMB(g_h_hi), *h_lo = SYMB(g_h_lo);
    bf16 *WdT_hi = SYMB(g_WdT_hi), *WdT_lo = SYMB(g_WdT_lo);
    bf16 *WqcrT_hi = SYMB(g_WqcrT_hi), *WqcrT_lo = SYMB(g_WqcrT_lo);
    bf16 *WkvcT_hi = SYMB(g_WkvcT_hi), *WkvcT_lo = SYMB(g_WkvcT_lo);
    bf16 *WoT_hi  = SYMB(g_WoT_hi),  *WoT_lo  = SYMB(g_WoT_lo);
    bf16 *cQ_hi = SYMB(g_cQ_hi), *cQ_lo = SYMB(g_cQ_lo);
    bf16 *cKV_hi = SYMB(g_cKV_hi), *cKV_lo = SYMB(g_cKV_lo);
    bf16 *qf_hi = SYMB(g_qf_hi), *qf_lo = SYMB(g_qf_lo);
    bf16 *kf_hi = SYMB(g_kf_hi), *kf_lo = SYMB(g_kf_lo);
    bf16 *vCT_hi = SYMB(g_vCT_hi), *vCT_lo = SYMB(g_vCT_lo);
    bf16 *w_hi = SYMB(g_w_hi), *w_lo = SYMB(g_w_lo);
    bf16 *attn_hi = SYMB(g_attn_hi), *attn_lo = SYMB(g_attn_lo);

    cudaFuncSetAttribute((const void*)gemm512<0,false>, cudaFuncAttributeMaxDynamicSharedMemorySize, G512_SMEM);
    cudaFuncSetAttribute((const void*)gemm512<2,true>,  cudaFuncAttributeMaxDynamicSharedMemorySize, G512_SMEM);
    cudaFuncSetAttribute(score_gemm, cudaFuncAttributeMaxDynamicSharedMemorySize, SCORE_SMEM);

    // prep: biases + splits for first merged GEMM (Wqd | Wkv | Wkr | pad)
    biascat<<<(N1 + 255)/256 > 16 ? (N1+255)/256 : 16, 256>>>(
        bq_down, bkv, bkr, bqc, bqr, bkc, bvc, b1, b2, b3);
    split_rm<<<(LL)NTOK*D_MODEL/1024, 256>>>(h, h_hi, h_lo);
    split_tr<<<dim3(D_CQ/32, D_MODEL/32), 256>>>(Wq_down, D_CQ, WdT_hi, WdT_lo, D_MODEL, D_CQ);
    split_tr<<<dim3(D_C/32, D_MODEL/32), 256>>>(Wkv, D_C,
        WdT_hi + (LL)D_CQ*D_MODEL, WdT_lo + (LL)D_CQ*D_MODEL, D_MODEL, D_C);
    split_tr<<<dim3(D_R/32, D_MODEL/32), 256>>>(Wkr, D_R,
        WdT_hi + (LL)2048*D_MODEL, WdT_lo + (LL)2048*D_MODEL, D_MODEL, D_R);
    zfill<<<(64*D_MODEL/2 + 255)/256, 256>>>(WdT_hi + (LL)2112*D_MODEL, (LL)64*D_MODEL);
    zfill<<<(64*D_MODEL/2 + 255)/256, 256>>>(WdT_lo + (LL)2112*D_MODEL, (LL)64*D_MODEL);

    // merged: tmp12 = h @ [Wq_down | Wkv | Wkr | 0] + bias   (N=2176)
    gemm512<0,false><<<dim3(N1/128, NTOK/256), 512, G512_SMEM>>>(
        h_hi, h_lo, WdT_hi, WdT_lo, b1, tmp12, nullptr, nullptr,
        D_MODEL, D_MODEL, D_MODEL, N1, 0,0,0,0,0,0,1);

    // remaining weight splits (merged buffers)
    split_tr<<<dim3(2048/32, D_CQ/32), 256>>>(Wqc, 2048, WqcrT_hi, WqcrT_lo, D_CQ, 2048);
    split_tr<<<dim3(1024/32, D_CQ/32), 256>>>(Wqr, 1024,
        WqcrT_hi + (LL)2048*D_CQ, WqcrT_lo + (LL)2048*D_CQ, D_CQ, 1024);
    split_tr<<<dim3(2048/32, D_C/32), 256>>>(Wkc, 2048, WkvcT_hi, WkvcT_lo, D_C, 2048);
    split_tr<<<dim3(2048/32, D_C/32), 256>>>(Wvc, 2048,
        WkvcT_hi + (LL)2048*D_C, WkvcT_lo + (LL)2048*D_C, D_C, 2048);
    split_tr<<<dim3(2048/32, 2048/32), 256>>>(Wo, 2048, WoT_hi, WoT_lo, 2048, 2048);

    // norms
    rmsnorm_split<<<NTOK, 256>>>(tmp12, N1, 0,    gq_norm, cQ_hi, cQ_lo, D_CQ);
    rmsnorm_split<<<NTOK, 256>>>(tmp12, N1, D_CQ, gkv,     cKV_hi, cKV_lo, D_C);
    rmsnorm_slice<<<NTOK, 256>>>(tmp12, N1, 2048, gkr, krn, D_R);

    // merged: qCR = cQ @ [Wqc | Wqr] + [bqc | bqr]   (N=3072)
    gemm512<0,false><<<dim3(3072/128, NTOK/256), 512, G512_SMEM>>>(
        cQ_hi, cQ_lo, WqcrT_hi, WqcrT_lo, b2, qCR, nullptr, nullptr,
        D_CQ, D_CQ, D_CQ, 3072, 0,0,0,0,0,0,1);

    // merged: kvC = cKV @ [Wkc | Wvc] + [bkc | bvc]   (N=4096)
    gemm512<0,false><<<dim3(4096/128, NTOK/256), 512, G512_SMEM>>>(
        cKV_hi, cKV_lo, WkvcT_hi, WkvcT_lo, b3, kvC, nullptr, nullptr,
        D_C, D_C, D_C, 4096, 0,0,0,0,0,0,1);

    // vC^T splits (vC = cols 2048..4095 of kvC)
    split_tr<<<dim3(2048/32, NTOK/32), 256>>>(kvC + 2048, 4096, vCT_hi, vCT_lo, NTOK, 2048);

    // pack + RoPE (q pre-scaled)
    pack_split<<<NTOK, 256>>>(qCR, kvC, krn, freqs, qf_hi, qf_lo, kf_hi, kf_lo,
                              1.0f / sqrtf((float)D_QK));

    // scores = q k^T (causal; upper tiles zero-fill w)
    score_gemm<<<dim3(SEQ/128, SEQ/128, BSZ*N_HEADS), 256, SCORE_SMEM>>>(
        qf_hi, qf_lo, kf_hi, kf_lo, w);

    // softmax (writes only k < kLim)
    softmax_kernel<<<(LL)BSZ*N_HEADS*SEQ, 256>>>(w, w_hi, w_lo);

    // PV: attn = w @ vC (K clipped at diagonal), bf16-split output
    {
        LL soW = (LL)N_HEADS * SEQ * SEQ, siW = (LL)SEQ * SEQ;
        LL soB = 2048;
        LL siB = (LL)D_H * NTOK;
        LL soC = (LL)SEQ * 2048, siC = D_H;
        gemm512<2,true><<<dim3(D_H/128, SEQ/256, BSZ*N_HEADS), 512, G512_SMEM>>>(
            w_hi, w_lo, vCT_hi, vCT_lo, nullptr, nullptr, attn_hi, attn_lo,
            SEQ, SEQ, NTOK, 2048,
            soW, siW, soB, siB, soC, siC, N_HEADS);
    }

    // h_out = attn @ Wo + bo
    gemm512<0,false><<<dim3(2048/128, NTOK/256), 512, G512_SMEM>>>(
        attn_hi, attn_lo, WoT_hi, WoT_lo, bo, out_h, nullptr, nullptr,
        2048, 2048, 2048, 2048, 0,0,0,0,0,0,1);
}